// round 3
// baseline (speedup 1.0000x reference)
#include <cuda_runtime.h>
#include <cuda_bf16.h>
#include <cstdint>
#include <cstddef>

#define B_    64
#define T_    512
#define Dd    1024
#define Hh    1024
#define G3    3072
#define MROWS 32768          // B_*T_
#define NCTA  128            // persistent CTAs (<=148 SMs -> co-resident)
#define KC    128            // recurrence k-chunk

// ---------------- device scratch (no allocation) ----------------
__device__ float g_xg[(size_t)MROWS * G3];     // input gates for current layer
__device__ float g_y0[(size_t)MROWS * Hh];     // layer-0 outputs
__device__ __nv_bfloat16 g_hhi[2][B_ * Hh];    // h hi plane, double buffered
__device__ __nv_bfloat16 g_hlo[2][B_ * Hh];    // h lo plane
__device__ unsigned g_cnt = 0;
__device__ unsigned g_gen = 0;

// ---------------- helpers ----------------
__device__ __forceinline__ void mma_bf16(float* c, const uint32_t* a, uint32_t b0, uint32_t b1) {
    asm volatile(
        "mma.sync.aligned.m16n8k16.row.col.f32.bf16.bf16.f32 "
        "{%0,%1,%2,%3}, {%4,%5,%6,%7}, {%8,%9}, {%0,%1,%2,%3};"
        : "+f"(c[0]), "+f"(c[1]), "+f"(c[2]), "+f"(c[3])
        : "r"(a[0]), "r"(a[1]), "r"(a[2]), "r"(a[3]), "r"(b0), "r"(b1));
}
__device__ __forceinline__ uint32_t ld32(const __nv_bfloat16* p) { return *(const uint32_t*)p; }
__device__ __forceinline__ void cpa16(void* s, const void* g) {
    unsigned sa = (unsigned)__cvta_generic_to_shared(s);
    asm volatile("cp.async.cg.shared.global [%0], [%1], 16;" :: "r"(sa), "l"(g));
}
#define CP_COMMIT() asm volatile("cp.async.commit_group;")

__device__ __forceinline__ void grid_barrier() {
    __syncthreads();
    if (threadIdx.x == 0) {
        __threadfence();
        unsigned g;
        asm volatile("ld.acquire.gpu.u32 %0, [%1];" : "=r"(g) : "l"(&g_gen));
        unsigned a = atomicAdd(&g_cnt, 1u);
        if (a == NCTA - 1) {
            g_cnt = 0;
            asm volatile("st.release.gpu.u32 [%0], %1;" :: "l"(&g_gen), "r"(g + 1));
        } else {
            unsigned cur;
            do { asm volatile("ld.acquire.gpu.u32 %0, [%1];" : "=r"(cur) : "l"(&g_gen)); }
            while (cur == g);
        }
    }
    __syncthreads();
}

// ============ phase GEMM: g_xg[M,3072] = A[M,1024] * W[3072,1024]^T + bias ============
#define GBM 128
#define GBN 64
#define GBK 32
#define GSTR (GBK + 8)

__global__ void __launch_bounds__(256, 2) gemm_xg_kernel(const float* __restrict__ Aext,
                                                         const float* __restrict__ W,
                                                         const float* __restrict__ bias) {
    const float* A = Aext ? Aext : g_y0;
    __shared__ __nv_bfloat16 sAhi[GBM * GSTR], sAlo[GBM * GSTR];
    __shared__ __nv_bfloat16 sBhi[GBN * GSTR], sBlo[GBN * GSTR];

    const int tid = threadIdx.x, lane = tid & 31, warp = tid >> 5;
    const int m0 = blockIdx.y * GBM, n0 = blockIdx.x * GBN;
    const int wm = (warp & 3) * 32, wn = (warp >> 2) * 32;
    const int g = lane >> 2, q2 = (lane & 3) * 2;

    float acc[2][4][4];
#pragma unroll
    for (int a = 0; a < 2; a++)
#pragma unroll
        for (int b = 0; b < 4; b++)
#pragma unroll
            for (int c = 0; c < 4; c++) acc[a][b][c] = 0.f;

    for (int kt = 0; kt < Dd / GBK; ++kt) {
        const int k0 = kt * GBK;
#pragma unroll
        for (int i = 0; i < 4; i++) {                       // A tile 128x32
            int f = tid + i * 256, r = f >> 3, c4 = (f & 7) * 4;
            float4 v = *(const float4*)(A + (size_t)(m0 + r) * Dd + k0 + c4);
            __nv_bfloat162 h01 = __floats2bfloat162_rn(v.x, v.y);
            __nv_bfloat162 h23 = __floats2bfloat162_rn(v.z, v.w);
            *(__nv_bfloat162*)&sAhi[r * GSTR + c4]     = h01;
            *(__nv_bfloat162*)&sAhi[r * GSTR + c4 + 2] = h23;
            *(__nv_bfloat162*)&sAlo[r * GSTR + c4] =
                __floats2bfloat162_rn(v.x - __bfloat162float(h01.x), v.y - __bfloat162float(h01.y));
            *(__nv_bfloat162*)&sAlo[r * GSTR + c4 + 2] =
                __floats2bfloat162_rn(v.z - __bfloat162float(h23.x), v.w - __bfloat162float(h23.y));
        }
#pragma unroll
        for (int i = 0; i < 2; i++) {                       // B tile 64x32
            int f = tid + i * 256, r = f >> 3, c4 = (f & 7) * 4;
            float4 v = *(const float4*)(W + (size_t)(n0 + r) * Dd + k0 + c4);
            __nv_bfloat162 h01 = __floats2bfloat162_rn(v.x, v.y);
            __nv_bfloat162 h23 = __floats2bfloat162_rn(v.z, v.w);
            *(__nv_bfloat162*)&sBhi[r * GSTR + c4]     = h01;
            *(__nv_bfloat162*)&sBhi[r * GSTR + c4 + 2] = h23;
            *(__nv_bfloat162*)&sBlo[r * GSTR + c4] =
                __floats2bfloat162_rn(v.x - __bfloat162float(h01.x), v.y - __bfloat162float(h01.y));
            *(__nv_bfloat162*)&sBlo[r * GSTR + c4 + 2] =
                __floats2bfloat162_rn(v.z - __bfloat162float(h23.x), v.w - __bfloat162float(h23.y));
        }
        __syncthreads();

#pragma unroll
        for (int kk = 0; kk < GBK; kk += 16) {
            uint32_t ahi[2][4], alo[2][4];
#pragma unroll
            for (int mt = 0; mt < 2; mt++) {
                const __nv_bfloat16* ph = &sAhi[(wm + mt * 16 + g) * GSTR + kk + q2];
                ahi[mt][0] = ld32(ph);            ahi[mt][1] = ld32(ph + 8 * GSTR);
                ahi[mt][2] = ld32(ph + 8);        ahi[mt][3] = ld32(ph + 8 * GSTR + 8);
                const __nv_bfloat16* pl = &sAlo[(wm + mt * 16 + g) * GSTR + kk + q2];
                alo[mt][0] = ld32(pl);            alo[mt][1] = ld32(pl + 8 * GSTR);
                alo[mt][2] = ld32(pl + 8);        alo[mt][3] = ld32(pl + 8 * GSTR + 8);
            }
#pragma unroll
            for (int nt = 0; nt < 4; nt++) {
                const __nv_bfloat16* pb = &sBhi[(wn + nt * 8 + g) * GSTR + kk + q2];
                uint32_t bh0 = ld32(pb), bh1 = ld32(pb + 8);
                const __nv_bfloat16* pbl = &sBlo[(wn + nt * 8 + g) * GSTR + kk + q2];
                uint32_t bl0 = ld32(pbl), bl1 = ld32(pbl + 8);
#pragma unroll
                for (int mt = 0; mt < 2; mt++) {
                    mma_bf16(acc[mt][nt], ahi[mt], bh0, bh1);
                    mma_bf16(acc[mt][nt], alo[mt], bh0, bh1);
                    mma_bf16(acc[mt][nt], ahi[mt], bl0, bl1);
                }
            }
        }
        __syncthreads();
    }
#pragma unroll
    for (int mt = 0; mt < 2; mt++) {
        int row = m0 + wm + mt * 16 + g;
#pragma unroll
        for (int nt = 0; nt < 4; nt++) {
            int col = n0 + wn + nt * 8 + q2;
            float b0 = __ldg(bias + col), b1 = __ldg(bias + col + 1);
            *(float2*)(g_xg + (size_t)row * G3 + col) =
                make_float2(acc[mt][nt][0] + b0, acc[mt][nt][1] + b1);
            *(float2*)(g_xg + (size_t)(row + 8) * G3 + col) =
                make_float2(acc[mt][nt][2] + b0, acc[mt][nt][3] + b1);
        }
    }
}

// ================= persistent recurrence =================
#define WSTR (Hh + 8)
#define CSTR (KC + 8)
#define RSMEM_BYTES ((2 * 24 * WSTR + 3 * 2 * 64 * CSTR) * 2)

__global__ void __launch_bounds__(128, 1) recur_kernel(const float* __restrict__ h0,
                                                       const float* __restrict__ w_hh,
                                                       const float* __restrict__ b_hh,
                                                       float* __restrict__ y_ext) {
    float* y = y_ext ? y_ext : g_y0;
    extern __shared__ __align__(16) __nv_bfloat16 smem[];
    __nv_bfloat16* sWhi = smem;
    __nv_bfloat16* sWlo = sWhi + 24 * WSTR;
    __nv_bfloat16* sHhi = sWlo + 24 * WSTR;        // [3][64][CSTR]
    __nv_bfloat16* sHlo = sHhi + 3 * 64 * CSTR;

    const int tid = threadIdx.x, lane = tid & 31, warp = tid >> 5;
    const int cb = blockIdx.x * 8;                  // owned h-column base
    const int g = lane >> 2, q2 = (lane & 3) * 2;
    const int b0 = warp * 16 + g, b1 = b0 + 8;      // batch rows
    const int n0 = cb + q2;                         // columns n0, n0+1

    // load + split W_hh rows (gate-major: [r cols][z cols][n cols])
    for (int f = tid; f < 24 * 256; f += 128) {
        int r = f >> 8, c4 = (f & 255) * 4;
        int grow = (r >> 3) * Hh + cb + (r & 7);
        float4 v = *(const float4*)(w_hh + (size_t)grow * Hh + c4);
        __nv_bfloat162 h01 = __floats2bfloat162_rn(v.x, v.y);
        __nv_bfloat162 h23 = __floats2bfloat162_rn(v.z, v.w);
        *(__nv_bfloat162*)&sWhi[r * WSTR + c4]     = h01;
        *(__nv_bfloat162*)&sWhi[r * WSTR + c4 + 2] = h23;
        *(__nv_bfloat162*)&sWlo[r * WSTR + c4] =
            __floats2bfloat162_rn(v.x - __bfloat162float(h01.x), v.y - __bfloat162float(h01.y));
        *(__nv_bfloat162*)&sWlo[r * WSTR + c4 + 2] =
            __floats2bfloat162_rn(v.z - __bfloat162float(h23.x), v.w - __bfloat162float(h23.y));
    }
    __syncthreads();

    float bh[3][2];
#pragma unroll
    for (int gg = 0; gg < 3; gg++) {
        bh[gg][0] = b_hh[gg * Hh + n0];
        bh[gg][1] = b_hh[gg * Hh + n0 + 1];
    }
    float hprev[4];
    hprev[0] = h0[b0 * Hh + n0];     hprev[1] = h0[b0 * Hh + n0 + 1];
    hprev[2] = h0[b1 * Hh + n0];     hprev[3] = h0[b1 * Hh + n0 + 1];

    const float* xgp0 = g_xg + (size_t)b0 * T_ * G3 + n0;
    const float* xgp1 = g_xg + (size_t)b1 * T_ * G3 + n0;

    for (int t = 0; t < T_; ++t) {
        const int pb = t & 1, nb = pb ^ 1;
        if (t) grid_barrier();

        float acc[3][4];
#pragma unroll
        for (int gg = 0; gg < 3; gg++)
#pragma unroll
            for (int i = 0; i < 4; i++) acc[gg][i] = 0.f;

        // issue first two chunks (full 64x128 bf16 per plane: 1024 x 16B segs)
#pragma unroll
        for (int ck = 0; ck < 2; ck++) {
#pragma unroll
            for (int i = 0; i < 8; i++) {
                int f = tid + (i << 7);              // 0..1023
                int row = f >> 4, seg = (f & 15) << 3;
                size_t go = (size_t)row * Hh + ck * KC + seg;
                cpa16(&sHhi[(ck * 64 + row) * CSTR + seg], &g_hhi[pb][go]);
                cpa16(&sHlo[(ck * 64 + row) * CSTR + seg], &g_hlo[pb][go]);
            }
            CP_COMMIT();
        }

        for (int c = 0; c < 8; ++c) {
            if (c < 6) asm volatile("cp.async.wait_group 1;");
            else       asm volatile("cp.async.wait_group 0;");
            __syncthreads();
            if (c + 2 < 8) {
                int sb2 = (c + 2) % 3;
#pragma unroll
                for (int i = 0; i < 8; i++) {
                    int f = tid + (i << 7);
                    int row = f >> 4, seg = (f & 15) << 3;
                    size_t go = (size_t)row * Hh + (c + 2) * KC + seg;
                    cpa16(&sHhi[(sb2 * 64 + row) * CSTR + seg], &g_hhi[pb][go]);
                    cpa16(&sHlo[(sb2 * 64 + row) * CSTR + seg], &g_hlo[pb][go]);
                }
                CP_COMMIT();
            }
            const int sb = c % 3;
#pragma unroll
            for (int kk = 0; kk < KC / 16; kk++) {
                const int kq = kk * 16 + q2;
                const __nv_bfloat16* ph = &sHhi[(sb * 64 + b0) * CSTR + kq];
                const __nv_bfloat16* pl = &sHlo[(sb * 64 + b0) * CSTR + kq];
                uint32_t ahi[4], alo[4];
                ahi[0] = ld32(ph);               ahi[1] = ld32(ph + 8 * CSTR);
                ahi[2] = ld32(ph + 8);           ahi[3] = ld32(ph + 8 * CSTR + 8);
                alo[0] = ld32(pl);               alo[1] = ld32(pl + 8 * CSTR);
                alo[2] = ld32(pl + 8);           alo[3] = ld32(pl + 8 * CSTR + 8);
                const int gcol = c * KC + kq;
#pragma unroll
                for (int gg = 0; gg < 3; gg++) {
                    const __nv_bfloat16* pwh = &sWhi[(gg * 8 + g) * WSTR + gcol];
                    const __nv_bfloat16* pwl = &sWlo[(gg * 8 + g) * WSTR + gcol];
                    uint32_t bhh0 = ld32(pwh), bhh1 = ld32(pwh + 8);
                    uint32_t bll0 = ld32(pwl), bll1 = ld32(pwl + 8);
                    mma_bf16(acc[gg], ahi, bhh0, bhh1);
                    mma_bf16(acc[gg], alo, bhh0, bhh1);
                    mma_bf16(acc[gg], ahi, bll0, bll1);
                }
            }
        }

        // gate math (per thread: rows b0,b1 x cols n0,n0+1)
        float2 xr0 = *(const float2*)(xgp0);
        float2 xz0 = *(const float2*)(xgp0 + Hh);
        float2 xn0 = *(const float2*)(xgp0 + 2 * Hh);
        float2 xr1 = *(const float2*)(xgp1);
        float2 xz1 = *(const float2*)(xgp1 + Hh);
        float2 xn1 = *(const float2*)(xgp1 + 2 * Hh);
        xgp0 += G3; xgp1 += G3;

        float hnew[4];
        const float xr[4] = {xr0.x, xr0.y, xr1.x, xr1.y};
        const float xz[4] = {xz0.x, xz0.y, xz1.x, xz1.y};
        const float xn[4] = {xn0.x, xn0.y, xn1.x, xn1.y};
#pragma unroll
        for (int i = 0; i < 4; i++) {
            const int ci = i & 1;
            float r = 1.f / (1.f + __expf(-(xr[i] + acc[0][i] + bh[0][ci])));
            float z = 1.f / (1.f + __expf(-(xz[i] + acc[1][i] + bh[1][ci])));
            float n = tanhf(xn[i] + r * (acc[2][i] + bh[2][ci]));
            hnew[i] = (1.f - z) * n + z * hprev[i];
            hprev[i] = hnew[i];
        }
        *(float2*)(y + ((size_t)(b0 * T_ + t)) * Hh + n0) = make_float2(hnew[0], hnew[1]);
        *(float2*)(y + ((size_t)(b1 * T_ + t)) * Hh + n0) = make_float2(hnew[2], hnew[3]);

        __nv_bfloat162 hi0 = __floats2bfloat162_rn(hnew[0], hnew[1]);
        __nv_bfloat162 hi1 = __floats2bfloat162_rn(hnew[2], hnew[3]);
        __nv_bfloat162 lo0 = __floats2bfloat162_rn(hnew[0] - __bfloat162float(hi0.x),
                                                   hnew[1] - __bfloat162float(hi0.y));
        __nv_bfloat162 lo1 = __floats2bfloat162_rn(hnew[2] - __bfloat162float(hi1.x),
                                                   hnew[3] - __bfloat162float(hi1.y));
        *(__nv_bfloat162*)&g_hhi[nb][b0 * Hh + n0] = hi0;
        *(__nv_bfloat162*)&g_hhi[nb][b1 * Hh + n0] = hi1;
        *(__nv_bfloat162*)&g_hlo[nb][b0 * Hh + n0] = lo0;
        *(__nv_bfloat162*)&g_hlo[nb][b1 * Hh + n0] = lo1;
    }
}

// ---------------- small kernels ----------------
__global__ void split_h_kernel(const float* __restrict__ h0) {
    int i = blockIdx.x * blockDim.x + threadIdx.x;
    if (i < B_ * Hh) {
        float v = h0[i];
        __nv_bfloat16 hi = __float2bfloat16(v);
        g_hhi[0][i] = hi;
        g_hlo[0][i] = __float2bfloat16(v - __bfloat162float(hi));
    }
}

__global__ void tail_kernel(const float* __restrict__ y1, float* __restrict__ outh) {
    int i = blockIdx.x * blockDim.x + threadIdx.x;   // 0 .. 2*B*H-1
    if (i >= 2 * B_ * Hh) return;
    int b = (i & (B_ * Hh - 1)) >> 10, c = i & 1023;
    size_t src = ((size_t)(b * T_ + (T_ - 1))) * Hh + c;
    outh[i] = (i < B_ * Hh) ? g_y0[src] : y1[src];
}

// ---------------- launch ----------------
extern "C" void kernel_launch(void* const* d_in, const int* in_sizes, int n_in,
                              void* d_out, int out_size) {
    const float* x      = (const float*)d_in[0];
    const float* hidden = (const float*)d_in[1];
    const float* w_ih0  = (const float*)d_in[2];
    const float* w_hh0  = (const float*)d_in[3];
    const float* b_ih0  = (const float*)d_in[4];
    const float* b_hh0  = (const float*)d_in[5];
    const float* w_ih1  = (const float*)d_in[6];
    const float* w_hh1  = (const float*)d_in[7];
    const float* b_ih1  = (const float*)d_in[8];
    const float* b_hh1  = (const float*)d_in[9];
    float* out = (float*)d_out;

    cudaFuncSetAttribute(recur_kernel, cudaFuncAttributeMaxDynamicSharedMemorySize, RSMEM_BYTES);

    dim3 ggrid(G3 / GBN, MROWS / GBM);

    // layer 0
    split_h_kernel<<<(B_ * Hh + 255) / 256, 256>>>(hidden);
    gemm_xg_kernel<<<ggrid, 256>>>(x, w_ih0, b_ih0);
    recur_kernel<<<NCTA, 128, RSMEM_BYTES>>>(hidden, w_hh0, b_hh0, nullptr);

    // layer 1
    split_h_kernel<<<(B_ * Hh + 255) / 256, 256>>>(hidden + B_ * Hh);
    gemm_xg_kernel<<<ggrid, 256>>>(nullptr, w_ih1, b_ih1);
    recur_kernel<<<NCTA, 128, RSMEM_BYTES>>>(hidden + B_ * Hh, w_hh1, b_hh1, out);

    // final hidden states (only if the output buffer includes them)
    if (out_size >= MROWS * Hh + 2 * B_ * Hh) {
        tail_kernel<<<(2 * B_ * Hh + 255) / 256, 256>>>(out, out + (size_t)MROWS * Hh);
    }
}

// round 4
// speedup vs baseline: 1.2783x; 1.2783x over previous
#include <cuda_runtime.h>
#include <cuda_fp16.h>
#include <cstdint>
#include <cstddef>

#define B_    64
#define T_    512
#define Dd    1024
#define Hh    1024
#define G3    3072
#define MROWS 32768          // B_*T_
#define NCTA  128            // persistent CTAs (<=148 SMs -> co-resident)
#define KC    128            // recurrence k-chunk

// ---------------- device scratch (no allocation) ----------------
__device__ float  g_xg[(size_t)MROWS * G3];      // input gates for current layer (fp32)
__device__ float  g_y0[(size_t)MROWS * Hh];      // layer-0 outputs fp32 (for h0 tail)
__device__ __half g_xf16[(size_t)MROWS * Dd];    // x as fp16
__device__ __half g_y0f16[(size_t)MROWS * Hh];   // layer-0 outputs fp16 (layer-1 GEMM input)
__device__ __half g_whi[(size_t)G3 * Dd];        // W_ih hi plane
__device__ __half g_wlo[(size_t)G3 * Dd];        // W_ih lo plane
__device__ __half g_hf16[2][B_ * Hh];            // h state fp16, double buffered
__device__ unsigned g_cnt = 0;
__device__ unsigned g_gen = 0;

// ---------------- helpers ----------------
__device__ __forceinline__ void mma_f16(float* c, const uint32_t* a, uint32_t b0, uint32_t b1) {
    asm volatile(
        "mma.sync.aligned.m16n8k16.row.col.f32.f16.f16.f32 "
        "{%0,%1,%2,%3}, {%4,%5,%6,%7}, {%8,%9}, {%0,%1,%2,%3};"
        : "+f"(c[0]), "+f"(c[1]), "+f"(c[2]), "+f"(c[3])
        : "r"(a[0]), "r"(a[1]), "r"(a[2]), "r"(a[3]), "r"(b0), "r"(b1));
}
__device__ __forceinline__ uint32_t ld32(const __half* p) { return *(const uint32_t*)p; }
__device__ __forceinline__ void cpa16(void* s, const void* g) {
    unsigned sa = (unsigned)__cvta_generic_to_shared(s);
    asm volatile("cp.async.cg.shared.global [%0], [%1], 16;" :: "r"(sa), "l"(g));
}
#define CP_COMMIT() asm volatile("cp.async.commit_group;")

__device__ __forceinline__ void grid_barrier() {
    __syncthreads();
    if (threadIdx.x == 0) {
        __threadfence();
        unsigned g;
        asm volatile("ld.acquire.gpu.u32 %0, [%1];" : "=r"(g) : "l"(&g_gen));
        unsigned a = atomicAdd(&g_cnt, 1u);
        if (a == NCTA - 1) {
            g_cnt = 0;
            asm volatile("st.release.gpu.u32 [%0], %1;" :: "l"(&g_gen), "r"(g + 1));
        } else {
            unsigned cur;
            do { asm volatile("ld.acquire.gpu.u32 %0, [%1];" : "=r"(cur) : "l"(&g_gen)); }
            while (cur == g);
        }
    }
    __syncthreads();
}

// ---------------- conversion pre-pass kernels ----------------
__global__ void convx_kernel(const float* __restrict__ x) {
    size_t i = ((size_t)blockIdx.x * blockDim.x + threadIdx.x) * 4;
    if (i < (size_t)MROWS * Dd) {
        float4 v = *(const float4*)(x + i);
        __half2 a = __floats2half2_rn(v.x, v.y);
        __half2 b = __floats2half2_rn(v.z, v.w);
        *(__half2*)&g_xf16[i]     = a;
        *(__half2*)&g_xf16[i + 2] = b;
    }
}

__global__ void splitw_kernel(const float* __restrict__ w) {
    size_t i = ((size_t)blockIdx.x * blockDim.x + threadIdx.x) * 4;
    if (i < (size_t)G3 * Dd) {
        float4 v = *(const float4*)(w + i);
        __half hx = __float2half_rn(v.x), hy = __float2half_rn(v.y);
        __half hz = __float2half_rn(v.z), hw = __float2half_rn(v.w);
        *(__half2*)&g_whi[i]     = __halves2half2(hx, hy);
        *(__half2*)&g_whi[i + 2] = __halves2half2(hz, hw);
        *(__half2*)&g_wlo[i] = __floats2half2_rn(v.x - __half2float(hx), v.y - __half2float(hy));
        *(__half2*)&g_wlo[i + 2] = __floats2half2_rn(v.z - __half2float(hz), v.w - __half2float(hw));
    }
}

__global__ void split_h_kernel(const float* __restrict__ h0) {
    int i = blockIdx.x * blockDim.x + threadIdx.x;
    if (i < B_ * Hh) g_hf16[0][i] = __float2half_rn(h0[i]);
}

// ============ phase GEMM: g_xg[M,3072] = A_f16[M,1024] * (Whi+Wlo)[3072,1024]^T + bias ============
#define GBM 128
#define GBN 64
#define GBK 32
#define GSTR 40              // 32 halves + 8 pad
#define GA_ST (GBM * GSTR)   // 5120 halves per A stage
#define GB_ST (GBN * GSTR)   // 2560 halves per B stage
#define GEMM_SMEM ((3 * (GA_ST + 2 * GB_ST)) * 2)   // 61440 bytes

__global__ void __launch_bounds__(256, 2) gemm_xg_kernel(int useY0,
                                                         const float* __restrict__ bias) {
    const __half* A = useY0 ? g_y0f16 : g_xf16;
    extern __shared__ __align__(16) __half gsm[];
    __half* sA  = gsm;                    // [3][GA_ST]
    __half* sBh = sA + 3 * GA_ST;         // [3][GB_ST]
    __half* sBl = sBh + 3 * GB_ST;        // [3][GB_ST]

    const int tid = threadIdx.x, lane = tid & 31, warp = tid >> 5;
    const int m0 = blockIdx.y * GBM, n0 = blockIdx.x * GBN;
    const int wm = (warp & 3) * 32, wn = (warp >> 2) * 32;
    const int g = lane >> 2, q2 = (lane & 3) * 2;

    float acc[2][4][4];
#pragma unroll
    for (int a = 0; a < 2; a++)
#pragma unroll
        for (int b = 0; b < 4; b++)
#pragma unroll
            for (int c = 0; c < 4; c++) acc[a][b][c] = 0.f;

    const int ar = tid >> 2, as = tid & 3;          // B fill: row, seg
    // fill lambda (A: 512 segs, B hi/lo: 256 segs each)
    auto fill = [&](int st, int kt) {
        const int k0 = kt * GBK;
#pragma unroll
        for (int i = 0; i < 2; i++) {
            int f = tid + i * 256;
            int row = f >> 2, s = f & 3;
            cpa16(sA + st * GA_ST + row * GSTR + s * 8,
                  A + (size_t)(m0 + row) * Dd + k0 + s * 8);
        }
        cpa16(sBh + st * GB_ST + ar * GSTR + as * 8,
              g_whi + (size_t)(n0 + ar) * Dd + k0 + as * 8);
        cpa16(sBl + st * GB_ST + ar * GSTR + as * 8,
              g_wlo + (size_t)(n0 + ar) * Dd + k0 + as * 8);
        CP_COMMIT();
    };

    fill(0, 0);
    fill(1, 1);

    for (int kt = 0; kt < Dd / GBK; ++kt) {
        asm volatile("cp.async.wait_group 1;");
        __syncthreads();
        if (kt + 2 < Dd / GBK) fill((kt + 2) % 3, kt + 2);
        const int st = kt % 3;
        const __half* pA  = sA  + st * GA_ST;
        const __half* pBh = sBh + st * GB_ST;
        const __half* pBl = sBl + st * GB_ST;
#pragma unroll
        for (int kk = 0; kk < GBK; kk += 16) {
            uint32_t af[2][4];
#pragma unroll
            for (int mt = 0; mt < 2; mt++) {
                const __half* p = pA + (wm + mt * 16 + g) * GSTR + kk + q2;
                af[mt][0] = ld32(p);          af[mt][1] = ld32(p + 8 * GSTR);
                af[mt][2] = ld32(p + 8);      af[mt][3] = ld32(p + 8 * GSTR + 8);
            }
#pragma unroll
            for (int nt = 0; nt < 4; nt++) {
                const __half* ph = pBh + (wn + nt * 8 + g) * GSTR + kk + q2;
                uint32_t bh0 = ld32(ph), bh1 = ld32(ph + 8);
                const __half* pl = pBl + (wn + nt * 8 + g) * GSTR + kk + q2;
                uint32_t bl0 = ld32(pl), bl1 = ld32(pl + 8);
#pragma unroll
                for (int mt = 0; mt < 2; mt++) {
                    mma_f16(acc[mt][nt], af[mt], bh0, bh1);
                    mma_f16(acc[mt][nt], af[mt], bl0, bl1);
                }
            }
        }
        __syncthreads();
    }
#pragma unroll
    for (int mt = 0; mt < 2; mt++) {
        int row = m0 + wm + mt * 16 + g;
#pragma unroll
        for (int nt = 0; nt < 4; nt++) {
            int col = n0 + wn + nt * 8 + q2;
            float b0 = __ldg(bias + col), b1 = __ldg(bias + col + 1);
            *(float2*)(g_xg + (size_t)row * G3 + col) =
                make_float2(acc[mt][nt][0] + b0, acc[mt][nt][1] + b1);
            *(float2*)(g_xg + (size_t)(row + 8) * G3 + col) =
                make_float2(acc[mt][nt][2] + b0, acc[mt][nt][3] + b1);
        }
    }
}

// ================= persistent recurrence =================
#define WSTR (Hh + 8)
#define CSTR (KC + 8)
#define RSMEM_BYTES ((2 * 24 * WSTR + 3 * 64 * CSTR) * 2)

__global__ void __launch_bounds__(128, 1) recur_kernel(const float* __restrict__ h0,
                                                       const float* __restrict__ w_hh,
                                                       const float* __restrict__ b_hh,
                                                       float* __restrict__ y_ext) {
    float* y = y_ext ? y_ext : g_y0;
    const int writeF16 = (y_ext == nullptr);
    extern __shared__ __align__(16) __half smem[];
    __half* sWhi = smem;
    __half* sWlo = sWhi + 24 * WSTR;
    __half* sH   = sWlo + 24 * WSTR;          // [3][64][CSTR]

    const int tid = threadIdx.x, lane = tid & 31, warp = tid >> 5;
    const int cb = blockIdx.x * 8;             // owned h-column base
    const int g = lane >> 2, q2 = (lane & 3) * 2;
    const int b0 = warp * 16 + g, b1 = b0 + 8; // batch rows
    const int n0 = cb + q2;                    // columns n0, n0+1

    // load + split W_hh rows (gate-major: [r 8cols][z 8cols][n 8cols])
    for (int f = tid; f < 24 * 256; f += 128) {
        int r = f >> 8, c4 = (f & 255) * 4;
        int grow = (r >> 3) * Hh + cb + (r & 7);
        float4 v = *(const float4*)(w_hh + (size_t)grow * Hh + c4);
        __half hx = __float2half_rn(v.x), hy = __float2half_rn(v.y);
        __half hz = __float2half_rn(v.z), hw = __float2half_rn(v.w);
        *(__half2*)&sWhi[r * WSTR + c4]     = __halves2half2(hx, hy);
        *(__half2*)&sWhi[r * WSTR + c4 + 2] = __halves2half2(hz, hw);
        *(__half2*)&sWlo[r * WSTR + c4] =
            __floats2half2_rn(v.x - __half2float(hx), v.y - __half2float(hy));
        *(__half2*)&sWlo[r * WSTR + c4 + 2] =
            __floats2half2_rn(v.z - __half2float(hz), v.w - __half2float(hw));
    }
    __syncthreads();

    float bh[3][2];
#pragma unroll
    for (int gg = 0; gg < 3; gg++) {
        bh[gg][0] = b_hh[gg * Hh + n0];
        bh[gg][1] = b_hh[gg * Hh + n0 + 1];
    }
    float hprev[4];
    hprev[0] = h0[b0 * Hh + n0];     hprev[1] = h0[b0 * Hh + n0 + 1];
    hprev[2] = h0[b1 * Hh + n0];     hprev[3] = h0[b1 * Hh + n0 + 1];

    const float* xgp0 = g_xg + (size_t)b0 * T_ * G3 + n0;
    const float* xgp1 = g_xg + (size_t)b1 * T_ * G3 + n0;

    for (int t = 0; t < T_; ++t) {
        const int pb = t & 1, nb = pb ^ 1;
        if (t) grid_barrier();

        float acc[3][4];
#pragma unroll
        for (int gg = 0; gg < 3; gg++)
#pragma unroll
            for (int i = 0; i < 4; i++) acc[gg][i] = 0.f;

        // issue first two chunks (64 rows x 128 halves = 1024 x 16B segs each)
#pragma unroll
        for (int ck = 0; ck < 2; ck++) {
#pragma unroll
            for (int i = 0; i < 8; i++) {
                int f = tid + (i << 7);
                int row = f >> 4, sh = (f & 15) << 3;    // halves offset
                cpa16(&sH[(ck * 64 + row) * CSTR + sh],
                      &g_hf16[pb][row * Hh + ck * KC + sh]);
            }
            CP_COMMIT();
        }

        for (int c = 0; c < 8; ++c) {
            if (c < 6) asm volatile("cp.async.wait_group 1;");
            else       asm volatile("cp.async.wait_group 0;");
            __syncthreads();
            if (c + 2 < 8) {
                int sb2 = (c + 2) % 3;
#pragma unroll
                for (int i = 0; i < 8; i++) {
                    int f = tid + (i << 7);
                    int row = f >> 4, sh = (f & 15) << 3;
                    cpa16(&sH[(sb2 * 64 + row) * CSTR + sh],
                          &g_hf16[pb][row * Hh + (c + 2) * KC + sh]);
                }
                CP_COMMIT();
            }
            const int sb = c % 3;
#pragma unroll
            for (int kk = 0; kk < KC / 16; kk++) {
                const int kq = kk * 16 + q2;
                const __half* ph = &sH[(sb * 64 + b0) * CSTR + kq];
                uint32_t af[4];
                af[0] = ld32(ph);               af[1] = ld32(ph + 8 * CSTR);
                af[2] = ld32(ph + 8);           af[3] = ld32(ph + 8 * CSTR + 8);
                const int gcol = c * KC + kq;
#pragma unroll
                for (int gg = 0; gg < 3; gg++) {
                    const __half* pwh = &sWhi[(gg * 8 + g) * WSTR + gcol];
                    const __half* pwl = &sWlo[(gg * 8 + g) * WSTR + gcol];
                    uint32_t bh0 = ld32(pwh), bh1 = ld32(pwh + 8);
                    uint32_t bl0 = ld32(pwl), bl1 = ld32(pwl + 8);
                    mma_f16(acc[gg], af, bh0, bh1);
                    mma_f16(acc[gg], af, bl0, bl1);
                }
            }
        }

        // gate math (per thread: rows b0,b1 x cols n0,n0+1)
        float2 xr0 = *(const float2*)(xgp0);
        float2 xz0 = *(const float2*)(xgp0 + Hh);
        float2 xn0 = *(const float2*)(xgp0 + 2 * Hh);
        float2 xr1 = *(const float2*)(xgp1);
        float2 xz1 = *(const float2*)(xgp1 + Hh);
        float2 xn1 = *(const float2*)(xgp1 + 2 * Hh);
        xgp0 += G3; xgp1 += G3;

        float hnew[4];
        const float xr[4] = {xr0.x, xr0.y, xr1.x, xr1.y};
        const float xz[4] = {xz0.x, xz0.y, xz1.x, xz1.y};
        const float xn[4] = {xn0.x, xn0.y, xn1.x, xn1.y};
#pragma unroll
        for (int i = 0; i < 4; i++) {
            const int ci = i & 1;
            float r = 1.f / (1.f + __expf(-(xr[i] + acc[0][i] + bh[0][ci])));
            float z = 1.f / (1.f + __expf(-(xz[i] + acc[1][i] + bh[1][ci])));
            float n = tanhf(xn[i] + r * (acc[2][i] + bh[2][ci]));
            hnew[i] = (1.f - z) * n + z * hprev[i];
            hprev[i] = hnew[i];
        }
        *(float2*)(y + ((size_t)(b0 * T_ + t)) * Hh + n0) = make_float2(hnew[0], hnew[1]);
        *(float2*)(y + ((size_t)(b1 * T_ + t)) * Hh + n0) = make_float2(hnew[2], hnew[3]);
        if (writeF16) {
            *(__half2*)&g_y0f16[((size_t)(b0 * T_ + t)) * Hh + n0] =
                __floats2half2_rn(hnew[0], hnew[1]);
            *(__half2*)&g_y0f16[((size_t)(b1 * T_ + t)) * Hh + n0] =
                __floats2half2_rn(hnew[2], hnew[3]);
        }
        *(__half2*)&g_hf16[nb][b0 * Hh + n0] = __floats2half2_rn(hnew[0], hnew[1]);
        *(__half2*)&g_hf16[nb][b1 * Hh + n0] = __floats2half2_rn(hnew[2], hnew[3]);
    }
}

// ---------------- tail: final hidden states ----------------
__global__ void tail_kernel(const float* __restrict__ y1, float* __restrict__ outh) {
    int i = blockIdx.x * blockDim.x + threadIdx.x;   // 0 .. 2*B*H-1
    if (i >= 2 * B_ * Hh) return;
    int b = (i & (B_ * Hh - 1)) >> 10, c = i & 1023;
    size_t src = ((size_t)(b * T_ + (T_ - 1))) * Hh + c;
    outh[i] = (i < B_ * Hh) ? g_y0[src] : y1[src];
}

// ---------------- launch ----------------
extern "C" void kernel_launch(void* const* d_in, const int* in_sizes, int n_in,
                              void* d_out, int out_size) {
    const float* x      = (const float*)d_in[0];
    const float* hidden = (const float*)d_in[1];
    const float* w_ih0  = (const float*)d_in[2];
    const float* w_hh0  = (const float*)d_in[3];
    const float* b_ih0  = (const float*)d_in[4];
    const float* b_hh0  = (const float*)d_in[5];
    const float* w_ih1  = (const float*)d_in[6];
    const float* w_hh1  = (const float*)d_in[7];
    const float* b_ih1  = (const float*)d_in[8];
    const float* b_hh1  = (const float*)d_in[9];
    float* out = (float*)d_out;

    cudaFuncSetAttribute(recur_kernel, cudaFuncAttributeMaxDynamicSharedMemorySize, RSMEM_BYTES);
    cudaFuncSetAttribute(gemm_xg_kernel, cudaFuncAttributeMaxDynamicSharedMemorySize, GEMM_SMEM);

    dim3 ggrid(G3 / GBN, MROWS / GBM);

    // layer 0
    convx_kernel<<<(MROWS * Dd / 4 + 255) / 256, 256>>>(x);
    splitw_kernel<<<(G3 * Dd / 4 + 255) / 256, 256>>>(w_ih0);
    split_h_kernel<<<(B_ * Hh + 255) / 256, 256>>>(hidden);
    gemm_xg_kernel<<<ggrid, 256, GEMM_SMEM>>>(0, b_ih0);
    recur_kernel<<<NCTA, 128, RSMEM_BYTES>>>(hidden, w_hh0, b_hh0, nullptr);

    // layer 1
    splitw_kernel<<<(G3 * Dd / 4 + 255) / 256, 256>>>(w_ih1);
    split_h_kernel<<<(B_ * Hh + 255) / 256, 256>>>(hidden + B_ * Hh);
    gemm_xg_kernel<<<ggrid, 256, GEMM_SMEM>>>(1, b_ih1);
    recur_kernel<<<NCTA, 128, RSMEM_BYTES>>>(hidden + B_ * Hh, w_hh1, b_hh1, out);

    // final hidden states (only if the output buffer includes them)
    if (out_size >= MROWS * Hh + 2 * B_ * Hh) {
        tail_kernel<<<(2 * B_ * Hh + 255) / 256, 256>>>(out, out + (size_t)MROWS * Hh);
    }
}

// round 5
// speedup vs baseline: 1.5707x; 1.2287x over previous
#include <cuda_runtime.h>
#include <cuda_fp16.h>
#include <cstdint>
#include <cstddef>

#define B_    64
#define T_    512
#define Dd    1024
#define Hh    1024
#define G3    3072
#define MROWS 32768          // B_*T_
#define NCTA  128            // persistent CTAs (<=148 SMs -> co-resident)
#define KC    128            // recurrence k-chunk

// ---------------- device scratch (no allocation) ----------------
__device__ float  g_xg[(size_t)MROWS * G3];      // input gates for current layer (fp32)
__device__ float  g_y0[(size_t)MROWS * Hh];      // layer-0 outputs fp32 (for h0 tail)
__device__ __half g_xf16[(size_t)MROWS * Dd];    // x as fp16
__device__ __half g_y0f16[(size_t)MROWS * Hh];   // layer-0 outputs fp16 (layer-1 GEMM input)
__device__ __half g_whi[(size_t)G3 * Dd];        // W_ih hi plane
__device__ __half g_wlo[(size_t)G3 * Dd];        // W_ih lo plane
__device__ __half g_hf16[2][B_ * Hh];            // h state fp16, double buffered
__device__ unsigned g_cnt = 0;
__device__ unsigned g_gen = 0;

// ---------------- helpers ----------------
__device__ __forceinline__ void mma_f16(float* c, const uint32_t* a, uint32_t b0, uint32_t b1) {
    asm volatile(
        "mma.sync.aligned.m16n8k16.row.col.f32.f16.f16.f32 "
        "{%0,%1,%2,%3}, {%4,%5,%6,%7}, {%8,%9}, {%0,%1,%2,%3};"
        : "+f"(c[0]), "+f"(c[1]), "+f"(c[2]), "+f"(c[3])
        : "r"(a[0]), "r"(a[1]), "r"(a[2]), "r"(a[3]), "r"(b0), "r"(b1));
}
__device__ __forceinline__ uint32_t ld32(const __half* p) { return *(const uint32_t*)p; }
__device__ __forceinline__ void ldsm_x4(uint32_t* r, const __half* p) {
    unsigned a = (unsigned)__cvta_generic_to_shared(p);
    asm volatile("ldmatrix.sync.aligned.m8n8.x4.shared.b16 {%0,%1,%2,%3}, [%4];"
                 : "=r"(r[0]), "=r"(r[1]), "=r"(r[2]), "=r"(r[3]) : "r"(a));
}
__device__ __forceinline__ void ldsm_x2(uint32_t* r, const __half* p) {
    unsigned a = (unsigned)__cvta_generic_to_shared(p);
    asm volatile("ldmatrix.sync.aligned.m8n8.x2.shared.b16 {%0,%1}, [%2];"
                 : "=r"(r[0]), "=r"(r[1]) : "r"(a));
}
__device__ __forceinline__ void cpa16(void* s, const void* g) {
    unsigned sa = (unsigned)__cvta_generic_to_shared(s);
    asm volatile("cp.async.cg.shared.global [%0], [%1], 16;" :: "r"(sa), "l"(g));
}
#define CP_COMMIT() asm volatile("cp.async.commit_group;")

__device__ __forceinline__ void grid_barrier() {
    __syncthreads();
    if (threadIdx.x == 0) {
        __threadfence();
        unsigned g;
        asm volatile("ld.acquire.gpu.u32 %0, [%1];" : "=r"(g) : "l"(&g_gen));
        unsigned a = atomicAdd(&g_cnt, 1u);
        if (a == NCTA - 1) {
            g_cnt = 0;
            asm volatile("st.release.gpu.u32 [%0], %1;" :: "l"(&g_gen), "r"(g + 1));
        } else {
            unsigned cur;
            do { asm volatile("ld.acquire.gpu.u32 %0, [%1];" : "=r"(cur) : "l"(&g_gen)); }
            while (cur == g);
        }
    }
    __syncthreads();
}

// ---------------- conversion pre-pass kernels ----------------
__global__ void convx_kernel(const float* __restrict__ x) {
    size_t i = ((size_t)blockIdx.x * blockDim.x + threadIdx.x) * 4;
    if (i < (size_t)MROWS * Dd) {
        float4 v = *(const float4*)(x + i);
        *(__half2*)&g_xf16[i]     = __floats2half2_rn(v.x, v.y);
        *(__half2*)&g_xf16[i + 2] = __floats2half2_rn(v.z, v.w);
    }
}

__global__ void splitw_kernel(const float* __restrict__ w) {
    size_t i = ((size_t)blockIdx.x * blockDim.x + threadIdx.x) * 4;
    if (i < (size_t)G3 * Dd) {
        float4 v = *(const float4*)(w + i);
        __half hx = __float2half_rn(v.x), hy = __float2half_rn(v.y);
        __half hz = __float2half_rn(v.z), hw = __float2half_rn(v.w);
        *(__half2*)&g_whi[i]     = __halves2half2(hx, hy);
        *(__half2*)&g_whi[i + 2] = __halves2half2(hz, hw);
        *(__half2*)&g_wlo[i] = __floats2half2_rn(v.x - __half2float(hx), v.y - __half2float(hy));
        *(__half2*)&g_wlo[i + 2] = __floats2half2_rn(v.z - __half2float(hz), v.w - __half2float(hw));
    }
}

__global__ void split_h_kernel(const float* __restrict__ h0) {
    int i = blockIdx.x * blockDim.x + threadIdx.x;
    if (i < B_ * Hh) g_hf16[0][i] = __float2half_rn(h0[i]);
}

// ============ phase GEMM: g_xg[M,3072] = A_f16[M,1024] * (Whi+Wlo)[3072,1024]^T + bias ============
#define GBM 128
#define GBN 64
#define GBK 64
#define GSTR 72              // 64 halves + 8 pad
#define GA_ST (GBM * GSTR)   // 9216 halves per A stage
#define GB_ST (GBN * GSTR)   // 4608 halves per B stage
#define NKT   (Dd / GBK)     // 16
#define GEMM_SMEM ((3 * (GA_ST + 2 * GB_ST)) * 2)   // 110592 bytes

__global__ void __launch_bounds__(256, 2) gemm_xg_kernel(int useY0,
                                                         const float* __restrict__ bias) {
    const __half* A = useY0 ? g_y0f16 : g_xf16;
    extern __shared__ __align__(16) __half gsm[];
    __half* sA  = gsm;                    // [3][GA_ST]
    __half* sBh = sA + 3 * GA_ST;         // [3][GB_ST]
    __half* sBl = sBh + 3 * GB_ST;        // [3][GB_ST]

    const int tid = threadIdx.x, lane = tid & 31, warp = tid >> 5;
    const int m0 = blockIdx.y * GBM, n0 = blockIdx.x * GBN;
    const int wm = (warp & 3) * 32, wn = (warp >> 2) * 32;
    const int g = lane >> 2, q2 = (lane & 3) * 2;

    float acc[2][4][4];
#pragma unroll
    for (int a = 0; a < 2; a++)
#pragma unroll
        for (int b = 0; b < 4; b++)
#pragma unroll
            for (int c = 0; c < 4; c++) acc[a][b][c] = 0.f;

    auto fill = [&](int st, int kt) {
        const int k0 = kt * GBK;
#pragma unroll
        for (int i = 0; i < 4; i++) {                 // A: 128 rows x 8 segs
            int f = tid + i * 256, row = f >> 3, s = f & 7;
            cpa16(sA + st * GA_ST + row * GSTR + s * 8,
                  A + (size_t)(m0 + row) * Dd + k0 + s * 8);
        }
#pragma unroll
        for (int i = 0; i < 2; i++) {                 // B hi/lo: 64 rows x 8 segs
            int f = tid + i * 256, row = f >> 3, s = f & 7;
            cpa16(sBh + st * GB_ST + row * GSTR + s * 8,
                  g_whi + (size_t)(n0 + row) * Dd + k0 + s * 8);
            cpa16(sBl + st * GB_ST + row * GSTR + s * 8,
                  g_wlo + (size_t)(n0 + row) * Dd + k0 + s * 8);
        }
        CP_COMMIT();
    };

    fill(0, 0);
    fill(1, 1);

    for (int kt = 0; kt < NKT; ++kt) {
        if (kt + 2 < NKT) asm volatile("cp.async.wait_group 1;");
        else              asm volatile("cp.async.wait_group 0;");
        __syncthreads();
        if (kt + 2 < NKT) fill((kt + 2) % 3, kt + 2);
        const int st = kt % 3;
        const __half* pA  = sA  + st * GA_ST;
        const __half* pBh = sBh + st * GB_ST;
        const __half* pBl = sBl + st * GB_ST;
#pragma unroll
        for (int kk = 0; kk < GBK; kk += 16) {
            uint32_t af[2][4];
#pragma unroll
            for (int mt = 0; mt < 2; mt++) {
                const __half* p = pA + (wm + mt * 16 + g) * GSTR + kk + q2;
                af[mt][0] = ld32(p);          af[mt][1] = ld32(p + 8 * GSTR);
                af[mt][2] = ld32(p + 8);      af[mt][3] = ld32(p + 8 * GSTR + 8);
            }
#pragma unroll
            for (int nt = 0; nt < 4; nt++) {
                const __half* ph = pBh + (wn + nt * 8 + g) * GSTR + kk + q2;
                uint32_t bh0 = ld32(ph), bh1 = ld32(ph + 8);
                const __half* pl = pBl + (wn + nt * 8 + g) * GSTR + kk + q2;
                uint32_t bl0 = ld32(pl), bl1 = ld32(pl + 8);
#pragma unroll
                for (int mt = 0; mt < 2; mt++) {
                    mma_f16(acc[mt][nt], af[mt], bh0, bh1);
                    mma_f16(acc[mt][nt], af[mt], bl0, bl1);
                }
            }
        }
        __syncthreads();
    }
#pragma unroll
    for (int mt = 0; mt < 2; mt++) {
        int row = m0 + wm + mt * 16 + g;
#pragma unroll
        for (int nt = 0; nt < 4; nt++) {
            int col = n0 + wn + nt * 8 + q2;
            float b0 = __ldg(bias + col), b1 = __ldg(bias + col + 1);
            *(float2*)(g_xg + (size_t)row * G3 + col) =
                make_float2(acc[mt][nt][0] + b0, acc[mt][nt][1] + b1);
            *(float2*)(g_xg + (size_t)(row + 8) * G3 + col) =
                make_float2(acc[mt][nt][2] + b0, acc[mt][nt][3] + b1);
        }
    }
}

// ================= persistent recurrence (1-pass fp16 W_hh, ldmatrix) =================
#define WSTR (Hh + 8)
#define CSTR (KC + 8)
#define RSMEM_BYTES ((24 * WSTR + 3 * 64 * CSTR) * 2)

__global__ void __launch_bounds__(128, 1) recur_kernel(const float* __restrict__ h0,
                                                       const float* __restrict__ w_hh,
                                                       const float* __restrict__ b_hh,
                                                       float* __restrict__ y_ext) {
    float* y = y_ext ? y_ext : g_y0;
    const int writeF16 = (y_ext == nullptr);
    extern __shared__ __align__(16) __half smem[];
    __half* sW = smem;                       // [24][WSTR] fp16 hi only
    __half* sH = sW + 24 * WSTR;             // [3][64][CSTR]

    const int tid = threadIdx.x, lane = tid & 31, warp = tid >> 5;
    const int cb = blockIdx.x * 8;           // owned h-column base
    const int g = lane >> 2, q2 = (lane & 3) * 2;
    const int b0 = warp * 16 + g, b1 = b0 + 8;
    const int n0 = cb + q2;

    // load W_hh rows (gate-major: [r 8cols][z 8cols][n 8cols]) as fp16
    for (int f = tid; f < 24 * 256; f += 128) {
        int r = f >> 8, c4 = (f & 255) * 4;
        int grow = (r >> 3) * Hh + cb + (r & 7);
        float4 v = *(const float4*)(w_hh + (size_t)grow * Hh + c4);
        *(__half2*)&sW[r * WSTR + c4]     = __floats2half2_rn(v.x, v.y);
        *(__half2*)&sW[r * WSTR + c4 + 2] = __floats2half2_rn(v.z, v.w);
    }
    __syncthreads();

    float bh[3][2];
#pragma unroll
    for (int gg = 0; gg < 3; gg++) {
        bh[gg][0] = b_hh[gg * Hh + n0];
        bh[gg][1] = b_hh[gg * Hh + n0 + 1];
    }
    float hprev[4];
    hprev[0] = h0[b0 * Hh + n0];     hprev[1] = h0[b0 * Hh + n0 + 1];
    hprev[2] = h0[b1 * Hh + n0];     hprev[3] = h0[b1 * Hh + n0 + 1];

    const float* xgp0 = g_xg + (size_t)b0 * T_ * G3 + n0;
    const float* xgp1 = g_xg + (size_t)b1 * T_ * G3 + n0;

    // ldmatrix per-thread base offsets
    const int aRowSel = lane & 15, aColSel = (lane >> 4) << 3;   // A frag (x4)
    const int wRowSel = lane & 7,  wColSel = ((lane >> 3) & 1) << 3; // B frag (x2)

    for (int t = 0; t < T_; ++t) {
        const int pb = t & 1, nb = pb ^ 1;
        if (t) grid_barrier();

        // prefetch gate inputs early (independent of h)
        float2 xr0 = *(const float2*)(xgp0);
        float2 xz0 = *(const float2*)(xgp0 + Hh);
        float2 xn0 = *(const float2*)(xgp0 + 2 * Hh);
        float2 xr1 = *(const float2*)(xgp1);
        float2 xz1 = *(const float2*)(xgp1 + Hh);
        float2 xn1 = *(const float2*)(xgp1 + 2 * Hh);
        xgp0 += G3; xgp1 += G3;

        float acc[3][4];
#pragma unroll
        for (int gg = 0; gg < 3; gg++)
#pragma unroll
            for (int i = 0; i < 4; i++) acc[gg][i] = 0.f;

        // issue first two chunks (64 rows x 128 halves = 1024 x 16B segs each)
#pragma unroll
        for (int ck = 0; ck < 2; ck++) {
#pragma unroll
            for (int i = 0; i < 8; i++) {
                int f = tid + (i << 7);
                int row = f >> 4, sh = (f & 15) << 3;
                cpa16(&sH[(ck * 64 + row) * CSTR + sh],
                      &g_hf16[pb][row * Hh + ck * KC + sh]);
            }
            CP_COMMIT();
        }

        for (int c = 0; c < 8; ++c) {
            if (c < 6) asm volatile("cp.async.wait_group 1;");
            else       asm volatile("cp.async.wait_group 0;");
            __syncthreads();
            if (c + 2 < 8) {
                int sb2 = (c + 2) % 3;
#pragma unroll
                for (int i = 0; i < 8; i++) {
                    int f = tid + (i << 7);
                    int row = f >> 4, sh = (f & 15) << 3;
                    cpa16(&sH[(sb2 * 64 + row) * CSTR + sh],
                          &g_hf16[pb][row * Hh + (c + 2) * KC + sh]);
                }
                CP_COMMIT();
            }
            const int sb = c % 3;
            const __half* aBase = &sH[(sb * 64 + (warp << 4) + aRowSel) * CSTR + aColSel];
#pragma unroll
            for (int kk = 0; kk < KC / 16; kk++) {
                uint32_t af[4];
                ldsm_x4(af, aBase + kk * 16);
                const int gcol = c * KC + kk * 16 + wColSel;
#pragma unroll
                for (int gg = 0; gg < 3; gg++) {
                    uint32_t w[2];
                    ldsm_x2(w, &sW[(gg * 8 + wRowSel) * WSTR + gcol]);
                    mma_f16(acc[gg], af, w[0], w[1]);
                }
            }
        }

        // gate math (per thread: rows b0,b1 x cols n0,n0+1)
        float hnew[4];
        const float xr[4] = {xr0.x, xr0.y, xr1.x, xr1.y};
        const float xz[4] = {xz0.x, xz0.y, xz1.x, xz1.y};
        const float xn[4] = {xn0.x, xn0.y, xn1.x, xn1.y};
#pragma unroll
        for (int i = 0; i < 4; i++) {
            const int ci = i & 1;
            float r = 1.f / (1.f + __expf(-(xr[i] + acc[0][i] + bh[0][ci])));
            float z = 1.f / (1.f + __expf(-(xz[i] + acc[1][i] + bh[1][ci])));
            float n = tanhf(xn[i] + r * (acc[2][i] + bh[2][ci]));
            hnew[i] = (1.f - z) * n + z * hprev[i];
            hprev[i] = hnew[i];
        }
        *(float2*)(y + ((size_t)(b0 * T_ + t)) * Hh + n0) = make_float2(hnew[0], hnew[1]);
        *(float2*)(y + ((size_t)(b1 * T_ + t)) * Hh + n0) = make_float2(hnew[2], hnew[3]);
        if (writeF16) {
            *(__half2*)&g_y0f16[((size_t)(b0 * T_ + t)) * Hh + n0] =
                __floats2half2_rn(hnew[0], hnew[1]);
            *(__half2*)&g_y0f16[((size_t)(b1 * T_ + t)) * Hh + n0] =
                __floats2half2_rn(hnew[2], hnew[3]);
        }
        *(__half2*)&g_hf16[nb][b0 * Hh + n0] = __floats2half2_rn(hnew[0], hnew[1]);
        *(__half2*)&g_hf16[nb][b1 * Hh + n0] = __floats2half2_rn(hnew[2], hnew[3]);
    }
}

// ---------------- tail: final hidden states ----------------
__global__ void tail_kernel(const float* __restrict__ y1, float* __restrict__ outh) {
    int i = blockIdx.x * blockDim.x + threadIdx.x;   // 0 .. 2*B*H-1
    if (i >= 2 * B_ * Hh) return;
    int b = (i & (B_ * Hh - 1)) >> 10, c = i & 1023;
    size_t src = ((size_t)(b * T_ + (T_ - 1))) * Hh + c;
    outh[i] = (i < B_ * Hh) ? g_y0[src] : y1[src];
}

// ---------------- launch ----------------
extern "C" void kernel_launch(void* const* d_in, const int* in_sizes, int n_in,
                              void* d_out, int out_size) {
    const float* x      = (const float*)d_in[0];
    const float* hidden = (const float*)d_in[1];
    const float* w_ih0  = (const float*)d_in[2];
    const float* w_hh0  = (const float*)d_in[3];
    const float* b_ih0  = (const float*)d_in[4];
    const float* b_hh0  = (const float*)d_in[5];
    const float* w_ih1  = (const float*)d_in[6];
    const float* w_hh1  = (const float*)d_in[7];
    const float* b_ih1  = (const float*)d_in[8];
    const float* b_hh1  = (const float*)d_in[9];
    float* out = (float*)d_out;

    cudaFuncSetAttribute(recur_kernel, cudaFuncAttributeMaxDynamicSharedMemorySize, RSMEM_BYTES);
    cudaFuncSetAttribute(gemm_xg_kernel, cudaFuncAttributeMaxDynamicSharedMemorySize, GEMM_SMEM);

    dim3 ggrid(G3 / GBN, MROWS / GBM);

    // layer 0
    convx_kernel<<<(MROWS * Dd / 4 + 255) / 256, 256>>>(x);
    splitw_kernel<<<(G3 * Dd / 4 + 255) / 256, 256>>>(w_ih0);
    split_h_kernel<<<(B_ * Hh + 255) / 256, 256>>>(hidden);
    gemm_xg_kernel<<<ggrid, 256, GEMM_SMEM>>>(0, b_ih0);
    recur_kernel<<<NCTA, 128, RSMEM_BYTES>>>(hidden, w_hh0, b_hh0, nullptr);

    // layer 1
    splitw_kernel<<<(G3 * Dd / 4 + 255) / 256, 256>>>(w_ih1);
    split_h_kernel<<<(B_ * Hh + 255) / 256, 256>>>(hidden + B_ * Hh);
    gemm_xg_kernel<<<ggrid, 256, GEMM_SMEM>>>(1, b_ih1);
    recur_kernel<<<NCTA, 128, RSMEM_BYTES>>>(hidden + B_ * Hh, w_hh1, b_hh1, out);

    // final hidden states (only if the output buffer includes them)
    if (out_size >= MROWS * Hh + 2 * B_ * Hh) {
        tail_kernel<<<(2 * B_ * Hh + 255) / 256, 256>>>(out, out + (size_t)MROWS * Hh);
    }
}

// round 6
// speedup vs baseline: 1.8488x; 1.1771x over previous
#include <cuda_runtime.h>
#include <cuda_fp16.h>
#include <cstdint>
#include <cstddef>

#define B_    64
#define T_    512
#define Dd    1024
#define Hh    1024
#define G3    3072
#define MROWS 32768          // B_*T_
#define NCTA  128            // persistent CTAs (<=148 SMs -> co-resident)
#define KC    128            // recurrence k-chunk

// ---------------- device scratch (no allocation) ----------------
__device__ float  g_xg[(size_t)MROWS * G3];      // input gates for current layer (fp32)
__device__ __half g_xf16[(size_t)MROWS * Dd];    // x as fp16
__device__ __half g_y0f16[(size_t)MROWS * Hh];   // layer-0 outputs fp16 (layer-1 GEMM input)
__device__ __half g_whi[(size_t)G3 * Dd];        // W_ih fp16 plane
__device__ __half g_hf16[2][B_ * Hh];            // h state fp16, double buffered
__device__ float  g_h0last[B_ * Hh];             // layer-0 final hidden (fp32)
__device__ unsigned g_flags[NCTA * 32];          // one flag per 128B line

// ---------------- helpers ----------------
__device__ __forceinline__ void mma_f16(float* c, const uint32_t* a, uint32_t b0, uint32_t b1) {
    asm volatile(
        "mma.sync.aligned.m16n8k16.row.col.f32.f16.f16.f32 "
        "{%0,%1,%2,%3}, {%4,%5,%6,%7}, {%8,%9}, {%0,%1,%2,%3};"
        : "+f"(c[0]), "+f"(c[1]), "+f"(c[2]), "+f"(c[3])
        : "r"(a[0]), "r"(a[1]), "r"(a[2]), "r"(a[3]), "r"(b0), "r"(b1));
}
__device__ __forceinline__ void ldsm_x4(uint32_t* r, const __half* p) {
    unsigned a = (unsigned)__cvta_generic_to_shared(p);
    asm volatile("ldmatrix.sync.aligned.m8n8.x4.shared.b16 {%0,%1,%2,%3}, [%4];"
                 : "=r"(r[0]), "=r"(r[1]), "=r"(r[2]), "=r"(r[3]) : "r"(a));
}
__device__ __forceinline__ void ldsm_x2(uint32_t* r, const __half* p) {
    unsigned a = (unsigned)__cvta_generic_to_shared(p);
    asm volatile("ldmatrix.sync.aligned.m8n8.x2.shared.b16 {%0,%1}, [%2];"
                 : "=r"(r[0]), "=r"(r[1]) : "r"(a));
}
__device__ __forceinline__ void cpa16(void* s, const void* g) {
    unsigned sa = (unsigned)__cvta_generic_to_shared(s);
    asm volatile("cp.async.cg.shared.global [%0], [%1], 16;" :: "r"(sa), "l"(g));
}
#define CP_COMMIT() asm volatile("cp.async.commit_group;")

// flag-array grid barrier: arrival = own-line release store; wait = 128 parallel polls
__device__ __forceinline__ void grid_barrier(unsigned target, int cta, int tid) {
    __threadfence();
    __syncthreads();
    if (tid == 0)
        asm volatile("st.release.gpu.u32 [%0], %1;" :: "l"(&g_flags[cta * 32]), "r"(target));
    unsigned v;
    do { asm volatile("ld.acquire.gpu.u32 %0, [%1];" : "=r"(v) : "l"(&g_flags[tid * 32])); }
    while (v < target);
    __syncthreads();
}

// ---------------- conversion pre-pass kernels ----------------
__global__ void convx_kernel(const float* __restrict__ x) {
    size_t i = ((size_t)blockIdx.x * blockDim.x + threadIdx.x) * 4;
    if (i < (size_t)MROWS * Dd) {
        float4 v = *(const float4*)(x + i);
        *(__half2*)&g_xf16[i]     = __floats2half2_rn(v.x, v.y);
        *(__half2*)&g_xf16[i + 2] = __floats2half2_rn(v.z, v.w);
    }
}

__global__ void convw_kernel(const float* __restrict__ w) {
    size_t i = ((size_t)blockIdx.x * blockDim.x + threadIdx.x) * 4;
    if (i < (size_t)G3 * Dd) {
        float4 v = *(const float4*)(w + i);
        *(__half2*)&g_whi[i]     = __floats2half2_rn(v.x, v.y);
        *(__half2*)&g_whi[i + 2] = __floats2half2_rn(v.z, v.w);
    }
}

__global__ void split_h_kernel(const float* __restrict__ h0) {
    int i = blockIdx.x * blockDim.x + threadIdx.x;
    if (i < B_ * Hh) g_hf16[0][i] = __float2half_rn(h0[i]);
}

// ============ phase GEMM: g_xg[M,3072] = A_f16[M,1024] * Whi[3072,1024]^T + bias ============
#define GBM 128
#define GBN 64
#define GBK 64
#define GSTR 72              // 64 halves + 8 pad
#define GA_ST (GBM * GSTR)   // 9216 halves per A stage
#define GB_ST (GBN * GSTR)   // 4608 halves per B stage
#define NKT   (Dd / GBK)     // 16
#define GEMM_SMEM ((3 * (GA_ST + GB_ST)) * 2)   // 82944 bytes

__global__ void __launch_bounds__(256, 2) gemm_xg_kernel(int useY0,
                                                         const float* __restrict__ bias) {
    const __half* A = useY0 ? g_y0f16 : g_xf16;
    extern __shared__ __align__(16) __half gsm[];
    __half* sA = gsm;                    // [3][GA_ST]
    __half* sB = sA + 3 * GA_ST;         // [3][GB_ST]

    const int tid = threadIdx.x, lane = tid & 31, warp = tid >> 5;
    const int m0 = blockIdx.y * GBM, n0 = blockIdx.x * GBN;
    const int wm = (warp & 3) * 32, wn = (warp >> 2) * 32;
    const int g = lane >> 2, q2 = (lane & 3) * 2;

    const int aRow = lane & 15,                    aCol = (lane >> 4) << 3;
    const int bRow = ((lane >> 4) << 3) + (lane & 7), bCol = ((lane >> 3) & 1) << 3;

    float acc[2][4][4];
#pragma unroll
    for (int a = 0; a < 2; a++)
#pragma unroll
        for (int b = 0; b < 4; b++)
#pragma unroll
            for (int c = 0; c < 4; c++) acc[a][b][c] = 0.f;

    auto fill = [&](int st, int kt) {
        const int k0 = kt * GBK;
#pragma unroll
        for (int i = 0; i < 4; i++) {                 // A: 128 rows x 8 segs
            int f = tid + i * 256, row = f >> 3, s = f & 7;
            cpa16(sA + st * GA_ST + row * GSTR + s * 8,
                  A + (size_t)(m0 + row) * Dd + k0 + s * 8);
        }
#pragma unroll
        for (int i = 0; i < 2; i++) {                 // B: 64 rows x 8 segs
            int f = tid + i * 256, row = f >> 3, s = f & 7;
            cpa16(sB + st * GB_ST + row * GSTR + s * 8,
                  g_whi + (size_t)(n0 + row) * Dd + k0 + s * 8);
        }
        CP_COMMIT();
    };

    fill(0, 0);
    fill(1, 1);

    for (int kt = 0; kt < NKT; ++kt) {
        if (kt + 2 < NKT) asm volatile("cp.async.wait_group 1;");
        else              asm volatile("cp.async.wait_group 0;");
        __syncthreads();
        if (kt + 2 < NKT) fill((kt + 2) % 3, kt + 2);
        const int st = kt % 3;
        const __half* pA = sA + st * GA_ST;
        const __half* pB = sB + st * GB_ST;
#pragma unroll
        for (int kk = 0; kk < GBK; kk += 16) {
            uint32_t af[2][4];
#pragma unroll
            for (int mt = 0; mt < 2; mt++)
                ldsm_x4(af[mt], pA + (wm + mt * 16 + aRow) * GSTR + kk + aCol);
#pragma unroll
            for (int p = 0; p < 2; p++) {
                uint32_t bf[4];
                ldsm_x4(bf, pB + (wn + p * 16 + bRow) * GSTR + kk + bCol);
#pragma unroll
                for (int mt = 0; mt < 2; mt++) {
                    mma_f16(acc[mt][2 * p],     af[mt], bf[0], bf[1]);
                    mma_f16(acc[mt][2 * p + 1], af[mt], bf[2], bf[3]);
                }
            }
        }
        __syncthreads();
    }
#pragma unroll
    for (int mt = 0; mt < 2; mt++) {
        int row = m0 + wm + mt * 16 + g;
#pragma unroll
        for (int nt = 0; nt < 4; nt++) {
            int col = n0 + wn + nt * 8 + q2;
            float b0 = __ldg(bias + col), b1 = __ldg(bias + col + 1);
            *(float2*)(g_xg + (size_t)row * G3 + col) =
                make_float2(acc[mt][nt][0] + b0, acc[mt][nt][1] + b1);
            *(float2*)(g_xg + (size_t)(row + 8) * G3 + col) =
                make_float2(acc[mt][nt][2] + b0, acc[mt][nt][3] + b1);
        }
    }
}

// ================= persistent recurrence (1-pass fp16 W_hh, ldmatrix, 6-deep h pipe) =================
#define WSTR (Hh + 8)
#define CSTR (KC + 8)
#define NHBUF 6
#define RSMEM_BYTES ((24 * WSTR + NHBUF * 64 * CSTR) * 2)

__global__ void __launch_bounds__(128, 1) recur_kernel(const float* __restrict__ h0,
                                                       const float* __restrict__ w_hh,
                                                       const float* __restrict__ b_hh,
                                                       float* __restrict__ yout) {
    const int layer0 = (yout == nullptr);
    extern __shared__ __align__(16) __half smem[];
    __half* sW = smem;                       // [24][WSTR]
    __half* sH = sW + 24 * WSTR;             // [NHBUF][64][CSTR]

    const int tid = threadIdx.x, lane = tid & 31, warp = tid >> 5;
    const int cta = blockIdx.x;
    const int cb = cta * 8;                  // owned h-column base
    const int g = lane >> 2, q2 = (lane & 3) * 2;
    const int b0 = warp * 16 + g, b1 = b0 + 8;
    const int n0 = cb + q2;

    const unsigned base = g_flags[cta * 32];  // monotonic barrier base (replay-safe)

    // load W_hh rows (gate-major: [r 8cols][z 8cols][n 8cols]) as fp16
    for (int f = tid; f < 24 * 256; f += 128) {
        int r = f >> 8, c4 = (f & 255) * 4;
        int grow = (r >> 3) * Hh + cb + (r & 7);
        float4 v = *(const float4*)(w_hh + (size_t)grow * Hh + c4);
        *(__half2*)&sW[r * WSTR + c4]     = __floats2half2_rn(v.x, v.y);
        *(__half2*)&sW[r * WSTR + c4 + 2] = __floats2half2_rn(v.z, v.w);
    }
    __syncthreads();

    float bh[3][2];
#pragma unroll
    for (int gg = 0; gg < 3; gg++) {
        bh[gg][0] = b_hh[gg * Hh + n0];
        bh[gg][1] = b_hh[gg * Hh + n0 + 1];
    }
    float hprev[4];
    hprev[0] = h0[b0 * Hh + n0];     hprev[1] = h0[b0 * Hh + n0 + 1];
    hprev[2] = h0[b1 * Hh + n0];     hprev[3] = h0[b1 * Hh + n0 + 1];

    const float* xgp0 = g_xg + (size_t)b0 * T_ * G3 + n0;
    const float* xgp1 = g_xg + (size_t)b1 * T_ * G3 + n0;

    const int aRow = lane & 15,                      aCol = (lane >> 4) << 3;
    const int bRow = ((lane >> 4) << 3) + (lane & 7), bCol = ((lane >> 3) & 1) << 3;
    const int wRowSel = lane & 7;

    for (int t = 0; t < T_; ++t) {
        const int pb = t & 1, nb = pb ^ 1;
        if (t) grid_barrier(base + (unsigned)t, cta, tid);

        // issue first 4 chunks (each: 64 rows x 128 halves = 1024 x 16B segs)
#pragma unroll
        for (int ck = 0; ck < 4; ck++) {
#pragma unroll
            for (int i = 0; i < 8; i++) {
                int f = tid + (i << 7);
                int row = f >> 4, sh = (f & 15) << 3;
                cpa16(&sH[(ck * 64 + row) * CSTR + sh],
                      &g_hf16[pb][row * Hh + ck * KC + sh]);
            }
            CP_COMMIT();
        }

        // prefetch gate inputs (independent of h)
        float2 xr0 = *(const float2*)(xgp0);
        float2 xz0 = *(const float2*)(xgp0 + Hh);
        float2 xn0 = *(const float2*)(xgp0 + 2 * Hh);
        float2 xr1 = *(const float2*)(xgp1);
        float2 xz1 = *(const float2*)(xgp1 + Hh);
        float2 xn1 = *(const float2*)(xgp1 + 2 * Hh);
        xgp0 += G3; xgp1 += G3;

        float acc[3][4];
#pragma unroll
        for (int gg = 0; gg < 3; gg++)
#pragma unroll
            for (int i = 0; i < 4; i++) acc[gg][i] = 0.f;

#pragma unroll
        for (int c = 0; c < 8; ++c) {
            if (c + 4 < 8) {
                int sb2 = (c + 4) % NHBUF;
#pragma unroll
                for (int i = 0; i < 8; i++) {
                    int f = tid + (i << 7);
                    int row = f >> 4, sh = (f & 15) << 3;
                    cpa16(&sH[(sb2 * 64 + row) * CSTR + sh],
                          &g_hf16[pb][row * Hh + (c + 4) * KC + sh]);
                }
                CP_COMMIT();
            }
            if      (c < 4)  asm volatile("cp.async.wait_group 4;");
            else if (c == 4) asm volatile("cp.async.wait_group 3;");
            else if (c == 5) asm volatile("cp.async.wait_group 2;");
            else if (c == 6) asm volatile("cp.async.wait_group 1;");
            else             asm volatile("cp.async.wait_group 0;");
            __syncthreads();

            const int sb = c % NHBUF;
            const __half* aBase = &sH[(sb * 64 + (warp << 4) + aRow) * CSTR + aCol];
#pragma unroll
            for (int kk = 0; kk < KC / 16; kk++) {
                uint32_t af[4];
                ldsm_x4(af, aBase + kk * 16);
                const int gcol = c * KC + kk * 16;
                uint32_t w01[4], w2[2];
                ldsm_x4(w01, &sW[bRow * WSTR + gcol + bCol]);
                ldsm_x2(w2, &sW[(16 + wRowSel) * WSTR + gcol + bCol]);
                mma_f16(acc[0], af, w01[0], w01[1]);
                mma_f16(acc[1], af, w01[2], w01[3]);
                mma_f16(acc[2], af, w2[0], w2[1]);
            }
        }

        // gate math (per thread: rows b0,b1 x cols n0,n0+1)
        float hnew[4];
        const float xr[4] = {xr0.x, xr0.y, xr1.x, xr1.y};
        const float xz[4] = {xz0.x, xz0.y, xz1.x, xz1.y};
        const float xn[4] = {xn0.x, xn0.y, xn1.x, xn1.y};
#pragma unroll
        for (int i = 0; i < 4; i++) {
            const int ci = i & 1;
            float r = 1.f / (1.f + __expf(-(xr[i] + acc[0][i] + bh[0][ci])));
            float z = 1.f / (1.f + __expf(-(xz[i] + acc[1][i] + bh[1][ci])));
            float n = tanhf(xn[i] + r * (acc[2][i] + bh[2][ci]));
            hnew[i] = (1.f - z) * n + z * hprev[i];
            hprev[i] = hnew[i];
        }

        if (layer0) {
            *(__half2*)&g_y0f16[((size_t)(b0 * T_ + t)) * Hh + n0] =
                __floats2half2_rn(hnew[0], hnew[1]);
            *(__half2*)&g_y0f16[((size_t)(b1 * T_ + t)) * Hh + n0] =
                __floats2half2_rn(hnew[2], hnew[3]);
            if (t == T_ - 1) {
                *(float2*)&g_h0last[b0 * Hh + n0] = make_float2(hnew[0], hnew[1]);
                *(float2*)&g_h0last[b1 * Hh + n0] = make_float2(hnew[2], hnew[3]);
            }
        } else {
            *(float2*)(yout + ((size_t)(b0 * T_ + t)) * Hh + n0) = make_float2(hnew[0], hnew[1]);
            *(float2*)(yout + ((size_t)(b1 * T_ + t)) * Hh + n0) = make_float2(hnew[2], hnew[3]);
        }
        *(__half2*)&g_hf16[nb][b0 * Hh + n0] = __floats2half2_rn(hnew[0], hnew[1]);
        *(__half2*)&g_hf16[nb][b1 * Hh + n0] = __floats2half2_rn(hnew[2], hnew[3]);
    }
}

// ---------------- tail: final hidden states ----------------
__global__ void tail_kernel(const float* __restrict__ y1, float* __restrict__ outh) {
    int i = blockIdx.x * blockDim.x + threadIdx.x;   // 0 .. 2*B*H-1
    if (i >= 2 * B_ * Hh) return;
    if (i < B_ * Hh) {
        outh[i] = g_h0last[i];
    } else {
        int j = i - B_ * Hh;
        int b = j >> 10, c = j & 1023;
        outh[i] = y1[((size_t)(b * T_ + (T_ - 1))) * Hh + c];
    }
}

// ---------------- launch ----------------
extern "C" void kernel_launch(void* const* d_in, const int* in_sizes, int n_in,
                              void* d_out, int out_size) {
    const float* x      = (const float*)d_in[0];
    const float* hidden = (const float*)d_in[1];
    const float* w_ih0  = (const float*)d_in[2];
    const float* w_hh0  = (const float*)d_in[3];
    const float* b_ih0  = (const float*)d_in[4];
    const float* b_hh0  = (const float*)d_in[5];
    const float* w_ih1  = (const float*)d_in[6];
    const float* w_hh1  = (const float*)d_in[7];
    const float* b_ih1  = (const float*)d_in[8];
    const float* b_hh1  = (const float*)d_in[9];
    float* out = (float*)d_out;

    cudaFuncSetAttribute(recur_kernel, cudaFuncAttributeMaxDynamicSharedMemorySize, RSMEM_BYTES);
    cudaFuncSetAttribute(gemm_xg_kernel, cudaFuncAttributeMaxDynamicSharedMemorySize, GEMM_SMEM);

    dim3 ggrid(G3 / GBN, MROWS / GBM);

    // layer 0
    convx_kernel<<<(MROWS * Dd / 4 + 255) / 256, 256>>>(x);
    convw_kernel<<<(G3 * Dd / 4 + 255) / 256, 256>>>(w_ih0);
    split_h_kernel<<<(B_ * Hh + 255) / 256, 256>>>(hidden);
    gemm_xg_kernel<<<ggrid, 256, GEMM_SMEM>>>(0, b_ih0);
    recur_kernel<<<NCTA, 128, RSMEM_BYTES>>>(hidden, w_hh0, b_hh0, nullptr);

    // layer 1
    convw_kernel<<<(G3 * Dd / 4 + 255) / 256, 256>>>(w_ih1);
    split_h_kernel<<<(B_ * Hh + 255) / 256, 256>>>(hidden + B_ * Hh);
    gemm_xg_kernel<<<ggrid, 256, GEMM_SMEM>>>(1, b_ih1);
    recur_kernel<<<NCTA, 128, RSMEM_BYTES>>>(hidden + B_ * Hh, w_hh1, b_hh1, out);

    // final hidden states (only if the output buffer includes them)
    if (out_size >= MROWS * Hh + 2 * B_ * Hh) {
        tail_kernel<<<(2 * B_ * Hh + 255) / 256, 256>>>(out, out + (size_t)MROWS * Hh);
    }
}

// round 7
// speedup vs baseline: 2.5219x; 1.3641x over previous
#include <cuda_runtime.h>
#include <cuda_fp16.h>
#include <cstdint>
#include <cstddef>

#define B_    64
#define T_    512
#define Dd    1024
#define Hh    1024
#define G3    3072
#define MROWS 32768          // B_*T_
#define NCTA  128            // persistent CTAs (<=148 SMs -> co-resident)
#define KC    128            // recurrence k-chunk

// ---------------- device scratch (no allocation) ----------------
__device__ float  g_xg[(size_t)MROWS * G3];      // input gates for current layer (fp32)
__device__ __half g_xf16[(size_t)MROWS * Dd];    // x as fp16
__device__ __half g_y0f16[(size_t)MROWS * Hh];   // layer-0 outputs fp16 (layer-1 GEMM input)
__device__ __half g_whi[(size_t)G3 * Dd];        // W_ih fp16 plane
__device__ __half g_hf16[2][B_ * Hh];            // h state fp16, double buffered
__device__ float  g_h0last[B_ * Hh];             // layer-0 final hidden (fp32)
__device__ unsigned g_flags[NCTA * 32];          // one flag per 128B line

// ---------------- helpers ----------------
__device__ __forceinline__ void mma_f16(float* c, const uint32_t* a, uint32_t b0, uint32_t b1) {
    asm volatile(
        "mma.sync.aligned.m16n8k16.row.col.f32.f16.f16.f32 "
        "{%0,%1,%2,%3}, {%4,%5,%6,%7}, {%8,%9}, {%0,%1,%2,%3};"
        : "+f"(c[0]), "+f"(c[1]), "+f"(c[2]), "+f"(c[3])
        : "r"(a[0]), "r"(a[1]), "r"(a[2]), "r"(a[3]), "r"(b0), "r"(b1));
}
__device__ __forceinline__ void ldsm_x4(uint32_t* r, const __half* p) {
    unsigned a = (unsigned)__cvta_generic_to_shared(p);
    asm volatile("ldmatrix.sync.aligned.m8n8.x4.shared.b16 {%0,%1,%2,%3}, [%4];"
                 : "=r"(r[0]), "=r"(r[1]), "=r"(r[2]), "=r"(r[3]) : "r"(a));
}
__device__ __forceinline__ void ldsm_x2(uint32_t* r, const __half* p) {
    unsigned a = (unsigned)__cvta_generic_to_shared(p);
    asm volatile("ldmatrix.sync.aligned.m8n8.x2.shared.b16 {%0,%1}, [%2];"
                 : "=r"(r[0]), "=r"(r[1]) : "r"(a));
}
__device__ __forceinline__ void cpa16(void* s, const void* g) {
    unsigned sa = (unsigned)__cvta_generic_to_shared(s);
    asm volatile("cp.async.cg.shared.global [%0], [%1], 16;" :: "r"(sa), "l"(g));
}
#define CP_COMMIT() asm volatile("cp.async.commit_group;")

// ---------------- conversion pre-pass kernels ----------------
__global__ void convx_kernel(const float* __restrict__ x) {
    size_t i = ((size_t)blockIdx.x * blockDim.x + threadIdx.x) * 4;
    if (i < (size_t)MROWS * Dd) {
        float4 v = *(const float4*)(x + i);
        *(__half2*)&g_xf16[i]     = __floats2half2_rn(v.x, v.y);
        *(__half2*)&g_xf16[i + 2] = __floats2half2_rn(v.z, v.w);
    }
}

__global__ void convw_kernel(const float* __restrict__ w) {
    size_t i = ((size_t)blockIdx.x * blockDim.x + threadIdx.x) * 4;
    if (i < (size_t)G3 * Dd) {
        float4 v = *(const float4*)(w + i);
        *(__half2*)&g_whi[i]     = __floats2half2_rn(v.x, v.y);
        *(__half2*)&g_whi[i + 2] = __floats2half2_rn(v.z, v.w);
    }
}

__global__ void split_h_kernel(const float* __restrict__ h0) {
    int i = blockIdx.x * blockDim.x + threadIdx.x;
    if (i < B_ * Hh) g_hf16[0][i] = __float2half_rn(h0[i]);
}

// ============ phase GEMM: g_xg[M,3072] = A_f16[M,1024] * Whi[3072,1024]^T + bias ============
#define GBM 128
#define GBN 64
#define GBK 64
#define GSTR 72              // 64 halves + 8 pad
#define GA_ST (GBM * GSTR)
#define GB_ST (GBN * GSTR)
#define NKT   (Dd / GBK)     // 16
#define GEMM_SMEM ((3 * (GA_ST + GB_ST)) * 2)   // 82944 bytes

__global__ void __launch_bounds__(256, 2) gemm_xg_kernel(int useY0,
                                                         const float* __restrict__ bias) {
    const __half* A = useY0 ? g_y0f16 : g_xf16;
    extern __shared__ __align__(16) __half gsm[];
    __half* sA = gsm;                    // [3][GA_ST]
    __half* sB = sA + 3 * GA_ST;         // [3][GB_ST]

    const int tid = threadIdx.x, lane = tid & 31, warp = tid >> 5;
    const int m0 = blockIdx.y * GBM, n0 = blockIdx.x * GBN;
    const int wm = (warp & 3) * 32, wn = (warp >> 2) * 32;
    const int g = lane >> 2, q2 = (lane & 3) * 2;

    const int aRow = lane & 15,                    aCol = (lane >> 4) << 3;
    const int bRow = ((lane >> 4) << 3) + (lane & 7), bCol = ((lane >> 3) & 1) << 3;

    float acc[2][4][4];
#pragma unroll
    for (int a = 0; a < 2; a++)
#pragma unroll
        for (int b = 0; b < 4; b++)
#pragma unroll
            for (int c = 0; c < 4; c++) acc[a][b][c] = 0.f;

    auto fill = [&](int st, int kt) {
        const int k0 = kt * GBK;
#pragma unroll
        for (int i = 0; i < 4; i++) {
            int f = tid + i * 256, row = f >> 3, s = f & 7;
            cpa16(sA + st * GA_ST + row * GSTR + s * 8,
                  A + (size_t)(m0 + row) * Dd + k0 + s * 8);
        }
#pragma unroll
        for (int i = 0; i < 2; i++) {
            int f = tid + i * 256, row = f >> 3, s = f & 7;
            cpa16(sB + st * GB_ST + row * GSTR + s * 8,
                  g_whi + (size_t)(n0 + row) * Dd + k0 + s * 8);
        }
        CP_COMMIT();
    };

    fill(0, 0);
    fill(1, 1);

    for (int kt = 0; kt < NKT; ++kt) {
        if (kt + 2 < NKT) asm volatile("cp.async.wait_group 1;");
        else              asm volatile("cp.async.wait_group 0;");
        __syncthreads();
        if (kt + 2 < NKT) fill((kt + 2) % 3, kt + 2);
        const int st = kt % 3;
        const __half* pA = sA + st * GA_ST;
        const __half* pB = sB + st * GB_ST;
#pragma unroll
        for (int kk = 0; kk < GBK; kk += 16) {
            uint32_t af[2][4];
#pragma unroll
            for (int mt = 0; mt < 2; mt++)
                ldsm_x4(af[mt], pA + (wm + mt * 16 + aRow) * GSTR + kk + aCol);
#pragma unroll
            for (int p = 0; p < 2; p++) {
                uint32_t bf[4];
                ldsm_x4(bf, pB + (wn + p * 16 + bRow) * GSTR + kk + bCol);
#pragma unroll
                for (int mt = 0; mt < 2; mt++) {
                    mma_f16(acc[mt][2 * p],     af[mt], bf[0], bf[1]);
                    mma_f16(acc[mt][2 * p + 1], af[mt], bf[2], bf[3]);
                }
            }
        }
        __syncthreads();
    }
#pragma unroll
    for (int mt = 0; mt < 2; mt++) {
        int row = m0 + wm + mt * 16 + g;
#pragma unroll
        for (int nt = 0; nt < 4; nt++) {
            int col = n0 + wn + nt * 8 + q2;
            float b0 = __ldg(bias + col), b1 = __ldg(bias + col + 1);
            *(float2*)(g_xg + (size_t)row * G3 + col) =
                make_float2(acc[mt][nt][0] + b0, acc[mt][nt][1] + b1);
            *(float2*)(g_xg + (size_t)(row + 8) * G3 + col) =
                make_float2(acc[mt][nt][2] + b0, acc[mt][nt][3] + b1);
        }
    }
}

// ======== persistent recurrence: 2D partition (32 col-groups x 4 batch-groups), 256 thr ========
// CTA: cg = blockIdx.x & 31 (cols cg*32..+32), bg = blockIdx.x >> 5 (batch rows bg*16..+16)
// smem: W 96 rows (4 warp-blocks of [r8|z8|n8]) x (1024+8) halves, padded
//       sH 8 slots x 16 rows x 128 halves, XOR-swizzled (no pad)
#define WSTR2 1032
#define RSMEM2 ((96 * WSTR2 + 8 * 16 * 128) * 2)   // 230,912 bytes

__global__ void __launch_bounds__(256, 1) recur_kernel(const float* __restrict__ h0,
                                                       const float* __restrict__ w_hh,
                                                       const float* __restrict__ b_hh,
                                                       float* __restrict__ yout) {
    const int layer0 = (yout == nullptr);
    extern __shared__ __align__(16) __half smem[];
    __half* sW = smem;                       // [96][WSTR2]
    __half* sH = sW + 96 * WSTR2;            // [8][16][128] swizzled

    const int tid = threadIdx.x, lane = tid & 31, warp = tid >> 5;
    const int w4 = warp & 3, wg = warp >> 2;
    const int cg = blockIdx.x & 31, bg = blockIdx.x >> 5;
    const int gid = blockIdx.x;
    const int g = lane >> 2, q2 = (lane & 3) * 2;

    const unsigned base = g_flags[gid * 32];   // monotonic (replay-safe)

    // ---- load W_hh into smem: block layout rows = w4*24 + gate*8 + c8, cols = k
    for (int f = tid; f < 96 * 128; f += 256) {
        int rowp = f >> 7, seg = f & 127;
        int w4r = rowp / 24, rem = rowp - w4r * 24;
        int gate = rem >> 3, c8 = rem & 7;
        const float* src = w_hh + (size_t)(gate * Hh + cg * 32 + w4r * 8 + c8) * Hh + seg * 8;
        float4 v0 = *(const float4*)src;
        float4 v1 = *(const float4*)(src + 4);
        __half* d = sW + rowp * WSTR2 + seg * 8;
        ((__half2*)d)[0] = __floats2half2_rn(v0.x, v0.y);
        ((__half2*)d)[1] = __floats2half2_rn(v0.z, v0.w);
        ((__half2*)d)[2] = __floats2half2_rn(v1.x, v1.y);
        ((__half2*)d)[3] = __floats2half2_rn(v1.z, v1.w);
    }
    __syncthreads();

    // per-thread output coords (wg0 only does gate math)
    const int ncol = cg * 32 + w4 * 8 + q2;        // 2 cols: ncol, ncol+1
    const int rb0 = bg * 16 + g, rb1 = rb0 + 8;    // global batch rows

    float bh[3][2];
#pragma unroll
    for (int gg = 0; gg < 3; gg++) {
        bh[gg][0] = b_hh[gg * Hh + ncol];
        bh[gg][1] = b_hh[gg * Hh + ncol + 1];
    }
    float hprev[4];
    hprev[0] = h0[rb0 * Hh + ncol];     hprev[1] = h0[rb0 * Hh + ncol + 1];
    hprev[2] = h0[rb1 * Hh + ncol];     hprev[3] = h0[rb1 * Hh + ncol + 1];

    const float* xgp0 = g_xg + (size_t)rb0 * T_ * G3 + ncol;
    const float* xgp1 = g_xg + (size_t)rb1 * T_ * G3 + ncol;

    // fragment selectors
    const int aRow = lane & 15, aSeg = lane >> 4;                 // A: row, 16B-seg half
    const int bRow = ((lane >> 4) << 3) + (lane & 7), bCol = ((lane >> 3) & 1) << 3;
    const int nRow = lane & 7;
    const int myChunk = wg * 4 + w4;                              // chunk this warp streams
    const int kbase = wg * 512;                                   // K half offset
    const int wb = w4 * 24;                                       // W block row base

    for (int t = 0; t < T_; ++t) {
        const int pb = t & 1, nb = pb ^ 1;

        if (t) {  // barrier among the 32 CTAs sharing this bg
            __threadfence();
            __syncthreads();
            if (tid == 0)
                asm volatile("st.release.gpu.u32 [%0], %1;"
                             :: "l"(&g_flags[gid * 32]), "r"(base + (unsigned)t));
            if (tid < 32) {
                unsigned v;
                do { asm volatile("ld.acquire.gpu.u32 %0, [%1];"
                                  : "=r"(v) : "l"(&g_flags[(bg * 32 + tid) * 32])); }
                while (v < base + (unsigned)t);
            }
            __syncthreads();
        }

        // each warp streams its chunk (16 rows x 128 halves, swizzled), one commit group
        {
#pragma unroll
            for (int i = 0; i < 8; i++) {
                int f = lane + i * 32;               // 0..255
                int r = f >> 4, sj = f & 15;
                int sjs = sj ^ (r & 7);
                cpa16(sH + myChunk * 2048 + r * 128 + sjs * 8,
                      &g_hf16[pb][(size_t)(bg * 16 + r) * Hh + myChunk * KC + sj * 8]);
            }
            CP_COMMIT();
        }

        // prefetch gate inputs (wg0 only)
        float xr[4], xz[4], xn[4];
        if (wg == 0) {
            float2 a0 = *(const float2*)(xgp0);
            float2 a1 = *(const float2*)(xgp0 + Hh);
            float2 a2 = *(const float2*)(xgp0 + 2 * Hh);
            float2 b0v = *(const float2*)(xgp1);
            float2 b1v = *(const float2*)(xgp1 + Hh);
            float2 b2v = *(const float2*)(xgp1 + 2 * Hh);
            xr[0] = a0.x; xr[1] = a0.y; xr[2] = b0v.x; xr[3] = b0v.y;
            xz[0] = a1.x; xz[1] = a1.y; xz[2] = b1v.x; xz[3] = b1v.y;
            xn[0] = a2.x; xn[1] = a2.y; xn[2] = b2v.x; xn[3] = b2v.y;
        }
        xgp0 += G3; xgp1 += G3;

        float acc[3][4];
#pragma unroll
        for (int gg = 0; gg < 3; gg++)
#pragma unroll
            for (int i = 0; i < 4; i++) acc[gg][i] = 0.f;

#pragma unroll
        for (int j = 0; j < 4; ++j) {
            if (w4 == j) asm volatile("cp.async.wait_group 0;");
            __syncthreads();
            const int slot = wg * 4 + j;
            const __half* hBase = sH + slot * 2048 + aRow * 128;
            const int sw = (aRow & 7);
#pragma unroll
            for (int kk = 0; kk < 8; kk++) {
                uint32_t af[4];
                int seg = kk * 2 + aSeg;
                ldsm_x4(af, hBase + (seg ^ sw) * 8);
                const int gcol = kbase + j * KC + kk * 16;
                uint32_t w01[4], w2[2];
                ldsm_x4(w01, sW + (wb + bRow) * WSTR2 + gcol + bCol);
                ldsm_x2(w2,  sW + (wb + 16 + nRow) * WSTR2 + gcol + bCol);
                mma_f16(acc[0], af, w01[0], w01[1]);
                mma_f16(acc[1], af, w01[2], w01[3]);
                mma_f16(acc[2], af, w2[0], w2[1]);
            }
        }

        // K-split reduction: wg1 -> smem scratch -> wg0 adds
        __syncthreads();
        float* scratch = (float*)sH;
        if (wg == 1) {
#pragma unroll
            for (int gg = 0; gg < 3; gg++)
#pragma unroll
                for (int i = 0; i < 4; i++)
                    scratch[(w4 * 32 + lane) * 12 + gg * 4 + i] = acc[gg][i];
        }
        __syncthreads();

        if (wg == 0) {
#pragma unroll
            for (int gg = 0; gg < 3; gg++)
#pragma unroll
                for (int i = 0; i < 4; i++)
                    acc[gg][i] += scratch[(w4 * 32 + lane) * 12 + gg * 4 + i];

            float hnew[4];
#pragma unroll
            for (int i = 0; i < 4; i++) {
                const int ci = i & 1;
                float r = 1.f / (1.f + __expf(-(xr[i] + acc[0][i] + bh[0][ci])));
                float z = 1.f / (1.f + __expf(-(xz[i] + acc[1][i] + bh[1][ci])));
                float n = tanhf(xn[i] + r * (acc[2][i] + bh[2][ci]));
                hnew[i] = (1.f - z) * n + z * hprev[i];
                hprev[i] = hnew[i];
            }

            if (layer0) {
                *(__half2*)&g_y0f16[((size_t)(rb0 * T_ + t)) * Hh + ncol] =
                    __floats2half2_rn(hnew[0], hnew[1]);
                *(__half2*)&g_y0f16[((size_t)(rb1 * T_ + t)) * Hh + ncol] =
                    __floats2half2_rn(hnew[2], hnew[3]);
                if (t == T_ - 1) {
                    *(float2*)&g_h0last[rb0 * Hh + ncol] = make_float2(hnew[0], hnew[1]);
                    *(float2*)&g_h0last[rb1 * Hh + ncol] = make_float2(hnew[2], hnew[3]);
                }
            } else {
                *(float2*)(yout + ((size_t)(rb0 * T_ + t)) * Hh + ncol) =
                    make_float2(hnew[0], hnew[1]);
                *(float2*)(yout + ((size_t)(rb1 * T_ + t)) * Hh + ncol) =
                    make_float2(hnew[2], hnew[3]);
            }
            *(__half2*)&g_hf16[nb][rb0 * Hh + ncol] = __floats2half2_rn(hnew[0], hnew[1]);
            *(__half2*)&g_hf16[nb][rb1 * Hh + ncol] = __floats2half2_rn(hnew[2], hnew[3]);
        }
    }
}

// ---------------- tail: final hidden states ----------------
__global__ void tail_kernel(const float* __restrict__ y1, float* __restrict__ outh) {
    int i = blockIdx.x * blockDim.x + threadIdx.x;   // 0 .. 2*B*H-1
    if (i >= 2 * B_ * Hh) return;
    if (i < B_ * Hh) {
        outh[i] = g_h0last[i];
    } else {
        int j = i - B_ * Hh;
        int b = j >> 10, c = j & 1023;
        outh[i] = y1[((size_t)(b * T_ + (T_ - 1))) * Hh + c];
    }
}

// ---------------- launch ----------------
extern "C" void kernel_launch(void* const* d_in, const int* in_sizes, int n_in,
                              void* d_out, int out_size) {
    const float* x      = (const float*)d_in[0];
    const float* hidden = (const float*)d_in[1];
    const float* w_ih0  = (const float*)d_in[2];
    const float* w_hh0  = (const float*)d_in[3];
    const float* b_ih0  = (const float*)d_in[4];
    const float* b_hh0  = (const float*)d_in[5];
    const float* w_ih1  = (const float*)d_in[6];
    const float* w_hh1  = (const float*)d_in[7];
    const float* b_ih1  = (const float*)d_in[8];
    const float* b_hh1  = (const float*)d_in[9];
    float* out = (float*)d_out;

    cudaFuncSetAttribute(recur_kernel, cudaFuncAttributeMaxDynamicSharedMemorySize, RSMEM2);
    cudaFuncSetAttribute(gemm_xg_kernel, cudaFuncAttributeMaxDynamicSharedMemorySize, GEMM_SMEM);

    dim3 ggrid(G3 / GBN, MROWS / GBM);

    // layer 0
    convx_kernel<<<(MROWS * Dd / 4 + 255) / 256, 256>>>(x);
    convw_kernel<<<(G3 * Dd / 4 + 255) / 256, 256>>>(w_ih0);
    split_h_kernel<<<(B_ * Hh + 255) / 256, 256>>>(hidden);
    gemm_xg_kernel<<<ggrid, 256, GEMM_SMEM>>>(0, b_ih0);
    recur_kernel<<<NCTA, 256, RSMEM2>>>(hidden, w_hh0, b_hh0, nullptr);

    // layer 1
    convw_kernel<<<(G3 * Dd / 4 + 255) / 256, 256>>>(w_ih1);
    split_h_kernel<<<(B_ * Hh + 255) / 256, 256>>>(hidden + B_ * Hh);
    gemm_xg_kernel<<<ggrid, 256, GEMM_SMEM>>>(1, b_ih1);
    recur_kernel<<<NCTA, 256, RSMEM2>>>(hidden + B_ * Hh, w_hh1, b_hh1, out);

    // final hidden states (only if the output buffer includes them)
    if (out_size >= MROWS * Hh + 2 * B_ * Hh) {
        tail_kernel<<<(2 * B_ * Hh + 255) / 256, 256>>>(out, out + (size_t)MROWS * Hh);
    }
}

// round 8
// speedup vs baseline: 2.8429x; 1.1273x over previous
#include <cuda_runtime.h>
#include <cuda_fp16.h>
#include <cstdint>
#include <cstddef>

#define B_    64
#define T_    512
#define Dd    1024
#define Hh    1024
#define G3    3072
#define MROWS 32768          // B_*T_
#define NCTA  128            // persistent CTAs (<=148 SMs -> co-resident)
#define KC    128            // recurrence k-chunk

// ---------------- device scratch (no allocation) ----------------
__device__ float  g_xg[(size_t)MROWS * G3];      // input gates for current layer (fp32)
__device__ __half g_xf16[(size_t)MROWS * Dd];    // x as fp16
__device__ __half g_y0f16[(size_t)MROWS * Hh];   // layer-0 outputs fp16 (layer-1 GEMM input)
__device__ __half g_whi[(size_t)G3 * Dd];        // W_ih fp16 plane
__device__ __half g_hf16[2][B_ * Hh];            // h state fp16, double buffered
__device__ float  g_h0last[B_ * Hh];             // layer-0 final hidden (fp32)
__device__ unsigned g_flags[NCTA * 32];          // one flag per 128B line

// ---------------- helpers ----------------
__device__ __forceinline__ void mma_f16(float* c, const uint32_t* a, uint32_t b0, uint32_t b1) {
    asm volatile(
        "mma.sync.aligned.m16n8k16.row.col.f32.f16.f16.f32 "
        "{%0,%1,%2,%3}, {%4,%5,%6,%7}, {%8,%9}, {%0,%1,%2,%3};"
        : "+f"(c[0]), "+f"(c[1]), "+f"(c[2]), "+f"(c[3])
        : "r"(a[0]), "r"(a[1]), "r"(a[2]), "r"(a[3]), "r"(b0), "r"(b1));
}
__device__ __forceinline__ void ldsm_x4(uint32_t* r, const __half* p) {
    unsigned a = (unsigned)__cvta_generic_to_shared(p);
    asm volatile("ldmatrix.sync.aligned.m8n8.x4.shared.b16 {%0,%1,%2,%3}, [%4];"
                 : "=r"(r[0]), "=r"(r[1]), "=r"(r[2]), "=r"(r[3]) : "r"(a));
}
__device__ __forceinline__ void ldsm_x2(uint32_t* r, const __half* p) {
    unsigned a = (unsigned)__cvta_generic_to_shared(p);
    asm volatile("ldmatrix.sync.aligned.m8n8.x2.shared.b16 {%0,%1}, [%2];"
                 : "=r"(r[0]), "=r"(r[1]) : "r"(a));
}
__device__ __forceinline__ void cpa16(void* s, const void* g) {
    unsigned sa = (unsigned)__cvta_generic_to_shared(s);
    asm volatile("cp.async.cg.shared.global [%0], [%1], 16;" :: "r"(sa), "l"(g));
}
#define CP_COMMIT() asm volatile("cp.async.commit_group;")

// ---------------- conversion pre-pass kernels ----------------
__global__ void convx_kernel(const float* __restrict__ x) {
    size_t i = ((size_t)blockIdx.x * blockDim.x + threadIdx.x) * 4;
    if (i < (size_t)MROWS * Dd) {
        float4 v = *(const float4*)(x + i);
        *(__half2*)&g_xf16[i]     = __floats2half2_rn(v.x, v.y);
        *(__half2*)&g_xf16[i + 2] = __floats2half2_rn(v.z, v.w);
    }
}

__global__ void convw_kernel(const float* __restrict__ w) {
    size_t i = ((size_t)blockIdx.x * blockDim.x + threadIdx.x) * 4;
    if (i < (size_t)G3 * Dd) {
        float4 v = *(const float4*)(w + i);
        *(__half2*)&g_whi[i]     = __floats2half2_rn(v.x, v.y);
        *(__half2*)&g_whi[i + 2] = __floats2half2_rn(v.z, v.w);
    }
}

__global__ void split_h_kernel(const float* __restrict__ h0) {
    int i = blockIdx.x * blockDim.x + threadIdx.x;
    if (i < B_ * Hh) g_hf16[0][i] = __float2half_rn(h0[i]);
}

// ============ phase GEMM: g_xg[M,3072] = A_f16[M,1024] * Whi[3072,1024]^T + bias ============
#define GBM 128
#define GBN 128
#define GBK 64
#define GSTR 72              // 64 halves + 8 pad
#define GA_ST (GBM * GSTR)   // 9216
#define GB_ST (GBN * GSTR)   // 9216
#define NKT   (Dd / GBK)     // 16
#define GEMM_SMEM ((3 * (GA_ST + GB_ST)) * 2)   // 110592 bytes

__global__ void __launch_bounds__(256, 2) gemm_xg_kernel(int useY0,
                                                         const float* __restrict__ bias) {
    const __half* A = useY0 ? g_y0f16 : g_xf16;
    extern __shared__ __align__(16) __half gsm[];
    __half* sA = gsm;                    // [3][GA_ST]
    __half* sB = sA + 3 * GA_ST;         // [3][GB_ST]

    const int tid = threadIdx.x, lane = tid & 31, warp = tid >> 5;
    const int m0 = blockIdx.y * GBM, n0 = blockIdx.x * GBN;
    const int wm = (warp & 1) * 64, wn = (warp >> 1) * 32;
    const int g = lane >> 2, q2 = (lane & 3) * 2;

    const int aRow = lane & 15,                       aCol = (lane >> 4) << 3;
    const int bRow = ((lane >> 4) << 3) + (lane & 7), bCol = ((lane >> 3) & 1) << 3;

    float acc[4][4][4];
#pragma unroll
    for (int a = 0; a < 4; a++)
#pragma unroll
        for (int b = 0; b < 4; b++)
#pragma unroll
            for (int c = 0; c < 4; c++) acc[a][b][c] = 0.f;

    auto fill = [&](int st, int kt) {
        const int k0 = kt * GBK;
#pragma unroll
        for (int i = 0; i < 4; i++) {                  // A: 128 rows x 8 segs
            int f = tid + i * 256, row = f >> 3, s = f & 7;
            cpa16(sA + st * GA_ST + row * GSTR + s * 8,
                  A + (size_t)(m0 + row) * Dd + k0 + s * 8);
        }
#pragma unroll
        for (int i = 0; i < 4; i++) {                  // B: 128 rows x 8 segs
            int f = tid + i * 256, row = f >> 3, s = f & 7;
            cpa16(sB + st * GB_ST + row * GSTR + s * 8,
                  g_whi + (size_t)(n0 + row) * Dd + k0 + s * 8);
        }
        CP_COMMIT();
    };

    fill(0, 0);
    fill(1, 1);

    for (int kt = 0; kt < NKT; ++kt) {
        if (kt + 2 < NKT) asm volatile("cp.async.wait_group 1;");
        else              asm volatile("cp.async.wait_group 0;");
        __syncthreads();
        if (kt + 2 < NKT) fill((kt + 2) % 3, kt + 2);
        const int st = kt % 3;
        const __half* pA = sA + st * GA_ST;
        const __half* pB = sB + st * GB_ST;
#pragma unroll
        for (int kk = 0; kk < GBK; kk += 16) {
            uint32_t af[4][4];
#pragma unroll
            for (int mt = 0; mt < 4; mt++)
                ldsm_x4(af[mt], pA + (wm + mt * 16 + aRow) * GSTR + kk + aCol);
#pragma unroll
            for (int p = 0; p < 2; p++) {
                uint32_t bf[4];
                ldsm_x4(bf, pB + (wn + p * 16 + bRow) * GSTR + kk + bCol);
#pragma unroll
                for (int mt = 0; mt < 4; mt++) {
                    mma_f16(acc[mt][2 * p],     af[mt], bf[0], bf[1]);
                    mma_f16(acc[mt][2 * p + 1], af[mt], bf[2], bf[3]);
                }
            }
        }
        __syncthreads();
    }
#pragma unroll
    for (int mt = 0; mt < 4; mt++) {
        int row = m0 + wm + mt * 16 + g;
#pragma unroll
        for (int nt = 0; nt < 4; nt++) {
            int col = n0 + wn + nt * 8 + q2;
            float b0 = __ldg(bias + col), b1 = __ldg(bias + col + 1);
            *(float2*)(g_xg + (size_t)row * G3 + col) =
                make_float2(acc[mt][nt][0] + b0, acc[mt][nt][1] + b1);
            *(float2*)(g_xg + (size_t)(row + 8) * G3 + col) =
                make_float2(acc[mt][nt][2] + b0, acc[mt][nt][3] + b1);
        }
    }
}

// ======== persistent recurrence: 2D partition (32 col-groups x 4 batch-groups), 256 thr ========
// r,z-gate W fragments live in registers (loaded once); n-gate W stays in smem.
#define WSTR2 1032
#define RSMEM2 ((96 * WSTR2 + 8 * 16 * 128) * 2)   // 230,912 bytes

__global__ void __launch_bounds__(256, 1) recur_kernel(const float* __restrict__ h0,
                                                       const float* __restrict__ w_hh,
                                                       const float* __restrict__ b_hh,
                                                       float* __restrict__ yout) {
    const int layer0 = (yout == nullptr);
    extern __shared__ __align__(16) __half smem[];
    __half* sW = smem;                       // [96][WSTR2]
    __half* sH = sW + 96 * WSTR2;            // [8][16][128] swizzled

    const int tid = threadIdx.x, lane = tid & 31, warp = tid >> 5;
    const int w4 = warp & 3, wg = warp >> 2;
    const int cg = blockIdx.x & 31, bg = blockIdx.x >> 5;
    const int gid = blockIdx.x;
    const int g = lane >> 2, q2 = (lane & 3) * 2;

    const unsigned base = g_flags[gid * 32];   // monotonic (replay-safe)

    // ---- load W_hh into smem: block layout rows = w4*24 + gate*8 + c8, cols = k
    for (int f = tid; f < 96 * 128; f += 256) {
        int rowp = f >> 7, seg = f & 127;
        int w4r = rowp / 24, rem = rowp - w4r * 24;
        int gate = rem >> 3, c8 = rem & 7;
        const float* src = w_hh + (size_t)(gate * Hh + cg * 32 + w4r * 8 + c8) * Hh + seg * 8;
        float4 v0 = *(const float4*)src;
        float4 v1 = *(const float4*)(src + 4);
        __half* d = sW + rowp * WSTR2 + seg * 8;
        ((__half2*)d)[0] = __floats2half2_rn(v0.x, v0.y);
        ((__half2*)d)[1] = __floats2half2_rn(v0.z, v0.w);
        ((__half2*)d)[2] = __floats2half2_rn(v1.x, v1.y);
        ((__half2*)d)[3] = __floats2half2_rn(v1.z, v1.w);
    }
    __syncthreads();

    // fragment selectors
    const int aRow = lane & 15, aSeg = lane >> 4;
    const int bRow = ((lane >> 4) << 3) + (lane & 7), bCol = ((lane >> 3) & 1) << 3;
    const int nRow = lane & 7;
    const int myChunk = wg * 4 + w4;
    const int kbase = wg * 512;
    const int wb = w4 * 24;

    // ---- r,z-gate W fragments -> registers (once, reused all 512 steps)
    uint32_t wreg[32][4];
#pragma unroll
    for (int kk = 0; kk < 32; kk++)
        ldsm_x4(wreg[kk], sW + (wb + bRow) * WSTR2 + kbase + kk * 16 + bCol);

    // per-thread output coords (wg0 only does gate math)
    const int ncol = cg * 32 + w4 * 8 + q2;
    const int rb0 = bg * 16 + g, rb1 = rb0 + 8;

    float bh[3][2];
#pragma unroll
    for (int gg = 0; gg < 3; gg++) {
        bh[gg][0] = b_hh[gg * Hh + ncol];
        bh[gg][1] = b_hh[gg * Hh + ncol + 1];
    }
    float hprev[4];
    hprev[0] = h0[rb0 * Hh + ncol];     hprev[1] = h0[rb0 * Hh + ncol + 1];
    hprev[2] = h0[rb1 * Hh + ncol];     hprev[3] = h0[rb1 * Hh + ncol + 1];

    const float* xgp0 = g_xg + (size_t)rb0 * T_ * G3 + ncol;
    const float* xgp1 = g_xg + (size_t)rb1 * T_ * G3 + ncol;

    for (int t = 0; t < T_; ++t) {
        const int pb = t & 1, nb = pb ^ 1;

        if (t) {  // barrier among the 32 CTAs sharing this bg
            __threadfence();
            __syncthreads();
            if (tid == 0)
                asm volatile("st.release.gpu.u32 [%0], %1;"
                             :: "l"(&g_flags[gid * 32]), "r"(base + (unsigned)t));
            if (tid < 32) {
                unsigned v;
                do { asm volatile("ld.acquire.gpu.u32 %0, [%1];"
                                  : "=r"(v) : "l"(&g_flags[(bg * 32 + tid) * 32])); }
                while (v < base + (unsigned)t);
            }
            __syncthreads();
        }

        // each warp streams its chunk (16 rows x 128 halves, swizzled), one commit group
        {
#pragma unroll
            for (int i = 0; i < 8; i++) {
                int f = lane + i * 32;
                int r = f >> 4, sj = f & 15;
                int sjs = sj ^ (r & 7);
                cpa16(sH + myChunk * 2048 + r * 128 + sjs * 8,
                      &g_hf16[pb][(size_t)(bg * 16 + r) * Hh + myChunk * KC + sj * 8]);
            }
            CP_COMMIT();
        }

        // prefetch gate inputs (wg0 only)
        float xr[4], xz[4], xn[4];
        if (wg == 0) {
            float2 a0 = *(const float2*)(xgp0);
            float2 a1 = *(const float2*)(xgp0 + Hh);
            float2 a2 = *(const float2*)(xgp0 + 2 * Hh);
            float2 b0v = *(const float2*)(xgp1);
            float2 b1v = *(const float2*)(xgp1 + Hh);
            float2 b2v = *(const float2*)(xgp1 + 2 * Hh);
            xr[0] = a0.x; xr[1] = a0.y; xr[2] = b0v.x; xr[3] = b0v.y;
            xz[0] = a1.x; xz[1] = a1.y; xz[2] = b1v.x; xz[3] = b1v.y;
            xn[0] = a2.x; xn[1] = a2.y; xn[2] = b2v.x; xn[3] = b2v.y;
        }
        xgp0 += G3; xgp1 += G3;

        float acc[3][4];
#pragma unroll
        for (int gg = 0; gg < 3; gg++)
#pragma unroll
            for (int i = 0; i < 4; i++) acc[gg][i] = 0.f;

#pragma unroll
        for (int j = 0; j < 4; ++j) {
            if (w4 == j) asm volatile("cp.async.wait_group 0;");
            __syncthreads();
            const int slot = wg * 4 + j;
            const __half* hBase = sH + slot * 2048 + aRow * 128;
            const int sw = (aRow & 7);
#pragma unroll
            for (int kk = 0; kk < 8; kk++) {
                uint32_t af[4];
                int seg = kk * 2 + aSeg;
                ldsm_x4(af, hBase + (seg ^ sw) * 8);
                const int gcol = kbase + j * KC + kk * 16;
                uint32_t w2[2];
                ldsm_x2(w2, sW + (wb + 16 + nRow) * WSTR2 + gcol + bCol);
                const uint32_t* w01 = wreg[j * 8 + kk];
                mma_f16(acc[0], af, w01[0], w01[1]);
                mma_f16(acc[1], af, w01[2], w01[3]);
                mma_f16(acc[2], af, w2[0], w2[1]);
            }
        }

        // K-split reduction: wg1 -> smem scratch -> wg0 adds
        __syncthreads();
        float* scratch = (float*)sH;
        if (wg == 1) {
#pragma unroll
            for (int gg = 0; gg < 3; gg++)
#pragma unroll
                for (int i = 0; i < 4; i++)
                    scratch[(w4 * 32 + lane) * 12 + gg * 4 + i] = acc[gg][i];
        }
        __syncthreads();

        if (wg == 0) {
#pragma unroll
            for (int gg = 0; gg < 3; gg++)
#pragma unroll
                for (int i = 0; i < 4; i++)
                    acc[gg][i] += scratch[(w4 * 32 + lane) * 12 + gg * 4 + i];

            float hnew[4];
#pragma unroll
            for (int i = 0; i < 4; i++) {
                const int ci = i & 1;
                float r = 1.f / (1.f + __expf(-(xr[i] + acc[0][i] + bh[0][ci])));
                float z = 1.f / (1.f + __expf(-(xz[i] + acc[1][i] + bh[1][ci])));
                float n = tanhf(xn[i] + r * (acc[2][i] + bh[2][ci]));
                hnew[i] = (1.f - z) * n + z * hprev[i];
                hprev[i] = hnew[i];
            }

            if (layer0) {
                *(__half2*)&g_y0f16[((size_t)(rb0 * T_ + t)) * Hh + ncol] =
                    __floats2half2_rn(hnew[0], hnew[1]);
                *(__half2*)&g_y0f16[((size_t)(rb1 * T_ + t)) * Hh + ncol] =
                    __floats2half2_rn(hnew[2], hnew[3]);
                if (t == T_ - 1) {
                    *(float2*)&g_h0last[rb0 * Hh + ncol] = make_float2(hnew[0], hnew[1]);
                    *(float2*)&g_h0last[rb1 * Hh + ncol] = make_float2(hnew[2], hnew[3]);
                }
            } else {
                *(float2*)(yout + ((size_t)(rb0 * T_ + t)) * Hh + ncol) =
                    make_float2(hnew[0], hnew[1]);
                *(float2*)(yout + ((size_t)(rb1 * T_ + t)) * Hh + ncol) =
                    make_float2(hnew[2], hnew[3]);
            }
            *(__half2*)&g_hf16[nb][rb0 * Hh + ncol] = __floats2half2_rn(hnew[0], hnew[1]);
            *(__half2*)&g_hf16[nb][rb1 * Hh + ncol] = __floats2half2_rn(hnew[2], hnew[3]);
        }
    }
}

// ---------------- tail: final hidden states ----------------
__global__ void tail_kernel(const float* __restrict__ y1, float* __restrict__ outh) {
    int i = blockIdx.x * blockDim.x + threadIdx.x;   // 0 .. 2*B*H-1
    if (i >= 2 * B_ * Hh) return;
    if (i < B_ * Hh) {
        outh[i] = g_h0last[i];
    } else {
        int j = i - B_ * Hh;
        int b = j >> 10, c = j & 1023;
        outh[i] = y1[((size_t)(b * T_ + (T_ - 1))) * Hh + c];
    }
}

// ---------------- launch ----------------
extern "C" void kernel_launch(void* const* d_in, const int* in_sizes, int n_in,
                              void* d_out, int out_size) {
    const float* x      = (const float*)d_in[0];
    const float* hidden = (const float*)d_in[1];
    const float* w_ih0  = (const float*)d_in[2];
    const float* w_hh0  = (const float*)d_in[3];
    const float* b_ih0  = (const float*)d_in[4];
    const float* b_hh0  = (const float*)d_in[5];
    const float* w_ih1  = (const float*)d_in[6];
    const float* w_hh1  = (const float*)d_in[7];
    const float* b_ih1  = (const float*)d_in[8];
    const float* b_hh1  = (const float*)d_in[9];
    float* out = (float*)d_out;

    cudaFuncSetAttribute(recur_kernel, cudaFuncAttributeMaxDynamicSharedMemorySize, RSMEM2);
    cudaFuncSetAttribute(gemm_xg_kernel, cudaFuncAttributeMaxDynamicSharedMemorySize, GEMM_SMEM);

    dim3 ggrid(G3 / GBN, MROWS / GBM);

    // layer 0
    convx_kernel<<<(MROWS * Dd / 4 + 255) / 256, 256>>>(x);
    convw_kernel<<<(G3 * Dd / 4 + 255) / 256, 256>>>(w_ih0);
    split_h_kernel<<<(B_ * Hh + 255) / 256, 256>>>(hidden);
    gemm_xg_kernel<<<ggrid, 256, GEMM_SMEM>>>(0, b_ih0);
    recur_kernel<<<NCTA, 256, RSMEM2>>>(hidden, w_hh0, b_hh0, nullptr);

    // layer 1
    convw_kernel<<<(G3 * Dd / 4 + 255) / 256, 256>>>(w_ih1);
    split_h_kernel<<<(B_ * Hh + 255) / 256, 256>>>(hidden + B_ * Hh);
    gemm_xg_kernel<<<ggrid, 256, GEMM_SMEM>>>(1, b_ih1);
    recur_kernel<<<NCTA, 256, RSMEM2>>>(hidden + B_ * Hh, w_hh1, b_hh1, out);

    // final hidden states (only if the output buffer includes them)
    if (out_size >= MROWS * Hh + 2 * B_ * Hh) {
        tail_kernel<<<(2 * B_ * Hh + 255) / 256, 256>>>(out, out + (size_t)MROWS * Hh);
    }
}